// round 12
// baseline (speedup 1.0000x reference)
#include <cuda_runtime.h>
#include <math.h>

#define WREG_E 72  // ernn: Whh cols in registers (36 packed pairs)
#define WSM_E  80  // ernn: Whh cols in smem (thread-major, padded to 84)
#define WPAD_E 84
#define WREG_M 64  // mrnn: cols in registers (32 packed pairs)
#define WSM_M  88  // mrnn: cols in smem (thread-major, padded to 92)
#define WPAD_M 92

typedef unsigned long long ull;

__device__ __forceinline__ void fma2(ull& d, ull a, ull b) {
    asm("fma.rn.f32x2 %0, %1, %2, %0;" : "+l"(d) : "l"(a), "l"(b));
}
__device__ __forceinline__ float2 unpack2(ull v) {
    float2 r; asm("mov.b64 {%0,%1}, %2;" : "=f"(r.x), "=f"(r.y) : "l"(v)); return r;
}
__device__ __forceinline__ ull pack2(float lo, float hi) {
    ull p; asm("mov.b64 %0, {%1,%2};" : "=l"(p) : "f"(lo), "f"(hi)); return p;
}

// ------------------------------ scratch ------------------------------------
__device__ float g_xp[2][2][400*32*480];     // [seq][dir][(t*32+b)*480 + laneidx]
__device__ float g_enc[2][400*32*300];       // [(t*32+b)*300 + dir*150+j]
__device__ float g_qa[320*96*300];
__device__ float g_aw[320*96*300];
__device__ float g_xpm[2][96*320*450];       // [(l*320+n)*450+g]
__device__ float g_ans[320*300];
__device__ float g_WihL2[2][150*480*2];      // paired: [(e2*480+idx)*2+p] = Wih[row(idx)][2*e2+p]
__device__ float g_mWihT2[2][150*452*2];     // paired: [(d2*452+g)*2+p] = mWih[g][2*d2+p]
__device__ float g_WhhT[4][152*450];         // (slots 2,3 used: matchf,matchb)
__device__ float g_Wlane[2][152*480];        // enc Whh lane order: [e*480 + idx]
__device__ float g_WA2[150*300*2], g_WB2[150*300*2], g_WC2[150*300*2]; // paired [(d2*300+j)*2+p]
__device__ float g_cmask[32*400], g_qmask[32*64];
__device__ int   g_len[320];

// lane mapping: warp w (0..14), lane l (0..29): unit u = w*10 + l/3, gate q = l%3,
// Whh/Wih row = q*150 + u.

// ------------------------------ prep ---------------------------------------
__global__ void k_prep(const int* ctx, const int* ques, const int* ca,
                       const float* eWihf, const float* eWihb,
                       const float* eWhhf, const float* eWhhb,
                       const float* mWhhf, const float* mWhhb,
                       const float* mWihf, const float* mWihb,
                       const float* fusW) {
    int t0 = blockIdx.x*blockDim.x + threadIdx.x;
    int stride = gridDim.x*blockDim.x;
    // lane-ordered + e-paired enc Wih
    for (int i = t0; i < 2*150*480*2; i += stride) {
        int dir = i / (150*480*2);
        int rem = i % (150*480*2);
        int p = rem & 1, t = rem >> 1;
        int e2 = t / 480, idx = t % 480;
        int w = idx >> 5, l = idx & 31;
        float v = 0.f;
        if (l < 30) {
            int u = w*10 + l/3, q = l%3;
            int row = q*150 + u;
            v = (dir ? eWihb : eWihf)[row*300 + 2*e2 + p];
        }
        g_WihL2[dir][rem] = v;
    }
    // paired match Wih (transposed)
    for (int i = t0; i < 2*150*452*2; i += stride) {
        int dir = i / (150*452*2);
        int rem = i % (150*452*2);
        int p = rem & 1, t = rem >> 1;
        int d2 = t / 452, g = t % 452;
        float v = 0.f;
        if (g < 450) v = (dir ? mWihb : mWihf)[g*300 + 2*d2 + p];
        g_mWihT2[dir][rem] = v;
    }
    for (int i = t0; i < 152*450; i += stride) {
        int e = i/450, g = i%450;
        float c=0,d=0;
        if (e < 150) { c=mWhhf[g*150+e]; d=mWhhb[g*150+e]; }
        g_WhhT[2][i]=c; g_WhhT[3][i]=d;
    }
    // lane-ordered enc Whh
    for (int i = t0; i < 2*152*480; i += stride) {
        int dir = i / (152*480);
        int rem = i % (152*480);
        int e = rem / 480, idx = rem % 480;
        int w = idx >> 5, l = idx & 31;
        float v = 0.f;
        if (l < 30 && e < 150) {
            int u = w*10 + l/3, q = l%3;
            int row = q*150 + u;
            v = (dir ? eWhhb : eWhhf)[row*150 + e];
        }
        g_Wlane[dir][rem] = v;
    }
    // paired fusion weights
    for (int i = t0; i < 150*300*2; i += stride) {
        int p = i & 1, t = i >> 1;
        int d2 = t / 300, j = t % 300;
        int d = 2*d2 + p;
        const float* r = fusW + (size_t)j*1200;
        float w4 = r[900+d];
        g_WA2[i] = r[d] + w4;
        g_WB2[i] = r[300+d] - w4;
        g_WC2[i] = r[600+d];
    }
    for (int i = t0; i < 32*400; i += stride) g_cmask[i] = (ctx[i]!=0)?1.f:0.f;
    for (int i = t0; i < 32*64;  i += stride) g_qmask[i] = (ques[i]!=0)?1.f:0.f;
    for (int i = t0; i < 320; i += stride) {
        int bq = i/10;
        int c = 0;
        for (int t = 0; t < 64; t++) c += (ques[bq*64+t] != 0);
        int st = ca[i*2];
        int al = ca[i*2+1] - st;
        int len = al + c;
        if (len > 96) len = 96;
        g_len[i] = len;
    }
}

// ---------------------- encoder input projections --------------------------
// 2 groups of 16 batches to bound register pressure (acc2[16] = 32 regs).
__global__ void __launch_bounds__(480) k_xp(
        const int* __restrict__ ctx, const int* __restrict__ ques,
        const float* __restrict__ emb,
        const float* __restrict__ bihf, const float* __restrict__ bihb) {
    __shared__ float es[32][304];
    __shared__ int tok[32];
    int t = blockIdx.x;
    int seq = (t >= 400) ? 1 : 0;
    int ti = seq ? t-400 : t;
    int T = seq ? 64 : 400;
    const int* toks = seq ? ques : ctx;
    int tid = threadIdx.x;
    if (tid < 32) tok[tid] = toks[tid*T + ti];
    __syncthreads();
    for (int i = tid; i < 32*300; i += blockDim.x) {
        int b=i/300, e=i%300;
        es[b][e] = emb[(size_t)tok[b]*300 + e];
    }
    __syncthreads();
    int w = tid >> 5, l = tid & 31;
    bool active = (l < 30);
    int u = w*10 + l/3, q = l - (l/3)*3;
    int row = q*150 + u;
    for (int dir = 0; dir < 2; dir++) {
        const float* __restrict__ WT = g_WihL2[dir];
        float bias = active ? (dir ? bihb : bihf)[row] : 0.f;
        float* out = g_xp[seq][dir];
        for (int grp = 0; grp < 2; grp++) {
            int bb = grp*16;
            ull acc2[16];
            #pragma unroll
            for (int b=0;b<16;b++) acc2[b] = 0ull;
            for (int e2 = 0; e2 < 150; e2 += 2) {
                ull w2a = *(const ull*)&WT[(e2*480+tid)*2];
                ull w2b = *(const ull*)&WT[((e2+1)*480+tid)*2];
                #pragma unroll
                for (int b=0;b<16;b++) {
                    ulonglong2 v = *(const ulonglong2*)&es[bb+b][2*e2];
                    fma2(acc2[b], v.x, w2a);
                    fma2(acc2[b], v.y, w2b);
                }
            }
            #pragma unroll
            for (int b=0;b<16;b++) {
                float2 f = unpack2(acc2[b]);
                out[((size_t)ti*32+bb+b)*480 + tid] = bias + f.x + f.y;
            }
        }
    }
}

// ---------------------------- encoder GRU ----------------------------------
__global__ void __launch_bounds__(480) k_ernn(const float* __restrict__ bhhf,
                                              const float* __restrict__ bhhb) {
    extern __shared__ float sm[];
    float* Wsm = sm;                   // 480 * WPAD_E (thread-major)
    float* hbuf = sm + 480*WPAD_E;     // 2 * 152 (double buffer)
    float* msm = hbuf + 2*152;         // T masks
    int id = blockIdx.x;
    int seq = (id >= 64) ? 1 : 0;
    int r = seq ? id-64 : id;
    int dir = r >> 5, b = r & 31;
    int T = seq ? 64 : 400;
    const float* __restrict__ WL = g_Wlane[dir];
    const float* __restrict__ bhh = dir ? bhhb : bhhf;
    const float* __restrict__ xp = g_xp[seq][dir];
    float* out = g_enc[seq];
    const float* __restrict__ mask = seq ? g_qmask : g_cmask;
    int tid = threadIdx.x;
    int w = tid >> 5, l = tid & 31;
    bool active = (l < 30);
    int u = w*10 + l/3;
    int q = l - (l/3)*3;
    int row = q*150 + u;

    for (int i = tid; i < 480*WSM_E; i += 480) {
        int j = i / WSM_E, e = i % WSM_E;
        Wsm[j*WPAD_E + e] = WL[(WREG_E+e)*480 + j];
    }
    for (int i = tid; i < 2*152; i += 480) hbuf[i] = 0.f;
    for (int i = tid; i < T; i += 480) msm[i] = mask[b*T + i];
    ull wreg2[WREG_E/2];
    #pragma unroll
    for (int e2 = 0; e2 < WREG_E/2; e2++)
        wreg2[e2] = pack2(WL[(2*e2)*480 + tid], WL[(2*e2+1)*480 + tid]);
    float bias = active ? bhh[row] : 0.f;
    __syncthreads();

    const ulonglong2* wv = (const ulonglong2*)(Wsm + tid*WPAD_E);
    int cur = 0;
    int tt0 = dir ? (T-1) : 0;
    float xnext = xp[((size_t)tt0*32+b)*480 + tid];
    for (int s = 0; s < T; s++) {
        int tt = dir ? (T-1-s) : s;
        float xg = xnext;
        const float* hcur = hbuf + cur*152;
        ull a0 = 0ull, a1 = 0ull, a2 = 0ull, a3 = 0ull;
        #pragma unroll
        for (int e = 0; e < WREG_E; e += 8) {
            ulonglong2 h1 = *(const ulonglong2*)&hcur[e];
            ulonglong2 h2 = *(const ulonglong2*)&hcur[e+4];
            fma2(a0, h1.x, wreg2[e/2]);
            fma2(a1, h1.y, wreg2[e/2+1]);
            fma2(a2, h2.x, wreg2[e/2+2]);
            fma2(a3, h2.y, wreg2[e/2+3]);
        }
        #pragma unroll
        for (int e = 0; e < WSM_E; e += 8) {
            ulonglong2 w1 = wv[e/4];
            ulonglong2 w2 = wv[e/4+1];
            ulonglong2 h1 = *(const ulonglong2*)&hcur[WREG_E+e];
            ulonglong2 h2 = *(const ulonglong2*)&hcur[WREG_E+e+4];
            fma2(a0, h1.x, w1.x);
            fma2(a1, h1.y, w1.y);
            fma2(a2, h2.x, w2.x);
            fma2(a3, h2.y, w2.y);
        }
        float2 f0 = unpack2(a0), f1 = unpack2(a1), f2 = unpack2(a2), f3 = unpack2(a3);
        float hd = bias + ((f0.x+f0.y)+(f1.x+f1.y)) + ((f2.x+f2.y)+(f3.x+f3.y));
        if (s + 1 < T) {
            int tn = dir ? (T-2-s) : (s+1);
            xnext = xp[((size_t)tn*32+b)*480 + tid];
        }
        int base = (l/3)*3;
        float hd_r = __shfl_sync(0xffffffffu, hd, base);
        float hd_z = __shfl_sync(0xffffffffu, hd, base+1);
        float hd_n = __shfl_sync(0xffffffffu, hd, base+2);
        float xg_r = __shfl_sync(0xffffffffu, xg, base);
        float xg_z = __shfl_sync(0xffffffffu, xg, base+1);
        float xg_n = __shfl_sync(0xffffffffu, xg, base+2);
        if (active) {
            float m  = msm[tt];
            float rr = 1.f/(1.f+expf(-(xg_r+hd_r)));
            float z  = 1.f/(1.f+expf(-(xg_z+hd_z)));
            float nn = tanhf(xg_n + rr*hd_n);
            float hp = hcur[u];
            float hnew = (1.f-z)*nn + z*hp;
            float o = m*hnew;
            if (q == 0) {
                hbuf[(cur^1)*152 + u] = o + (1.f-m)*hp;
                out[((size_t)tt*32+b)*300 + dir*150 + u] = o;
            }
        }
        cur ^= 1;
        __syncthreads();
    }
}

// -------------------- attention (with fused qa gather) ----------------------
__global__ void k_attn(const int* __restrict__ ca) {
    extern __shared__ float sm[];
    float* qa_s = sm;              // 32*304
    float* ceT  = sm + 32*304;     // 300*33
    float* sc   = ceT + 300*33;    // 32*400
    int n = blockIdx.x, lt = blockIdx.y, l0 = lt*32;
    int len = g_len[n];
    if (l0 >= len) return;
    int b = n/10;
    int st = ca[n*2], alen = ca[n*2+1] - st;
    int tid = threadIdx.x, warp = tid>>5, lane = tid&31;
    for (int i = tid; i < 32*300; i += 320) {
        int l = i/300, d = i%300;
        int gl = l0 + l;
        float v = 0.f;
        if (gl < len) {
            if (gl < alen) {
                int t = st + gl; if (t > 399) t = 399;
                v = g_enc[0][((size_t)t*32+b)*300 + d];
            } else {
                int t = gl - alen; if (t > 63) t = 63;
                v = g_enc[1][((size_t)t*32+b)*300 + d];
            }
        }
        qa_s[l*304+d] = v;
        g_qa[((size_t)n*96+gl)*300 + d] = v;
    }
    __syncthreads();
    // pass 1: scores
    for (int t0 = 0; t0 < 400; t0 += 32) {
        int tw = (400 - t0 < 32) ? (400 - t0) : 32;
        for (int i = tid; i < 32*300; i += 320) {
            int t = i/300, d = i%300;
            ceT[d*33+t] = (t < tw) ? g_enc[0][((size_t)(t0+t)*32+b)*300 + d] : 0.f;
        }
        __syncthreads();
        if (warp < 8) {
            int t = lane;
            float a0=0.f,a1=0.f,a2=0.f,a3=0.f;
            int L0=warp, L1=warp+8, L2=warp+16, L3=warp+24;
            #pragma unroll 4
            for (int d = 0; d < 300; d += 4) {
                float c0=ceT[d*33+t], c1=ceT[(d+1)*33+t], c2=ceT[(d+2)*33+t], c3=ceT[(d+3)*33+t];
                float4 qv;
                qv = *(float4*)&qa_s[L0*304+d]; a0 += qv.x*c0+qv.y*c1+qv.z*c2+qv.w*c3;
                qv = *(float4*)&qa_s[L1*304+d]; a1 += qv.x*c0+qv.y*c1+qv.z*c2+qv.w*c3;
                qv = *(float4*)&qa_s[L2*304+d]; a2 += qv.x*c0+qv.y*c1+qv.z*c2+qv.w*c3;
                qv = *(float4*)&qa_s[L3*304+d]; a3 += qv.x*c0+qv.y*c1+qv.z*c2+qv.w*c3;
            }
            if (t < tw) {
                float cm = g_cmask[b*400 + t0 + t];
                float big = -1e30f;
                sc[L0*400+t0+t] = cm>0.f ? a0 : big;
                sc[L1*400+t0+t] = cm>0.f ? a1 : big;
                sc[L2*400+t0+t] = cm>0.f ? a2 : big;
                sc[L3*400+t0+t] = cm>0.f ? a3 : big;
            }
        }
        __syncthreads();
    }
    // softmax per row
    for (int l = warp; l < 32; l += 10) {
        float mx = -1e30f;
        for (int t = lane; t < 400; t += 32) mx = fmaxf(mx, sc[l*400+t]);
        for (int o = 16; o; o >>= 1) mx = fmaxf(mx, __shfl_xor_sync(0xffffffffu, mx, o));
        float ss = 0.f;
        for (int t = lane; t < 400; t += 32) { float e = expf(sc[l*400+t]-mx); sc[l*400+t]=e; ss += e; }
        for (int o = 16; o; o >>= 1) ss += __shfl_xor_sync(0xffffffffu, ss, o);
        float inv = 1.f/ss;
        for (int t = lane; t < 400; t += 32) sc[l*400+t] *= inv;
    }
    __syncthreads();
    // pass 2: aware
    int d = tid;
    float acc[32];
    #pragma unroll
    for (int l = 0; l < 32; l++) acc[l] = 0.f;
    for (int t0 = 0; t0 < 400; t0 += 32) {
        int tw = (400 - t0 < 32) ? (400 - t0) : 32;
        for (int i = tid; i < 32*300; i += 320) {
            int t = i/300, dd = i%300;
            ceT[dd*33+t] = (t < tw) ? g_enc[0][((size_t)(t0+t)*32+b)*300 + dd] : 0.f;
        }
        __syncthreads();
        if (d < 300) {
            for (int t = 0; t < tw; t += 4) {
                float c0=ceT[d*33+t], c1=ceT[d*33+t+1], c2=ceT[d*33+t+2], c3=ceT[d*33+t+3];
                #pragma unroll
                for (int l = 0; l < 32; l++) {
                    float4 al = *(float4*)&sc[l*400 + t0 + t];
                    acc[l] += al.x*c0 + al.y*c1 + al.z*c2 + al.w*c3;
                }
            }
        }
        __syncthreads();
    }
    if (d < 300)
        for (int l = 0; l < 32; l++)
            g_aw[((size_t)n*96 + l0 + l)*300 + d] = acc[l];
}

// ------------------- fusion GEMM + match input projection ------------------
__global__ void __launch_bounds__(320) k_fuse(const float* __restrict__ fusb,
                       const float* __restrict__ mbihf, const float* __restrict__ mbihb) {
    extern __shared__ float sm[];
    float* qa_s = sm;               // 16*304
    float* aw_s = sm + 16*304;
    float* qw_s = aw_s + 16*304;
    float* m_s  = qw_s + 16*304;
    int n = blockIdx.x, lt = blockIdx.y, l0 = lt*16;
    if (l0 >= g_len[n]) return;
    int tid = threadIdx.x;
    for (int i = tid; i < 16*300; i += blockDim.x) {
        int l = i/300, d = i%300;
        float q = g_qa[((size_t)n*96 + l0 + l)*300 + d];
        float a = g_aw[((size_t)n*96 + l0 + l)*300 + d];
        qa_s[l*304+d] = q; aw_s[l*304+d] = a; qw_s[l*304+d] = q*a;
    }
    __syncthreads();
    int lg = tid/75, jg = tid%75, j0 = jg*4;
    if (tid < 300) {
        ull acc2[4][4];
        #pragma unroll
        for (int li=0; li<4; li++)
            #pragma unroll
            for (int j=0; j<4; j++) acc2[li][j] = 0ull;
        #pragma unroll 2
        for (int d2 = 0; d2 < 150; d2++) {
            int wo = (d2*300 + j0)*2;
            ulonglong2 wa01 = *(const ulonglong2*)&g_WA2[wo];
            ulonglong2 wa23 = *(const ulonglong2*)&g_WA2[wo+4];
            ulonglong2 wb01 = *(const ulonglong2*)&g_WB2[wo];
            ulonglong2 wb23 = *(const ulonglong2*)&g_WB2[wo+4];
            ulonglong2 wc01 = *(const ulonglong2*)&g_WC2[wo];
            ulonglong2 wc23 = *(const ulonglong2*)&g_WC2[wo+4];
            #pragma unroll
            for (int li = 0; li < 4; li++) {
                int l = lg*4 + li;
                ull q2 = *(const ull*)&qa_s[l*304 + 2*d2];
                ull a2 = *(const ull*)&aw_s[l*304 + 2*d2];
                ull w2 = *(const ull*)&qw_s[l*304 + 2*d2];
                fma2(acc2[li][0], q2, wa01.x); fma2(acc2[li][1], q2, wa01.y);
                fma2(acc2[li][2], q2, wa23.x); fma2(acc2[li][3], q2, wa23.y);
                fma2(acc2[li][0], a2, wb01.x); fma2(acc2[li][1], a2, wb01.y);
                fma2(acc2[li][2], a2, wb23.x); fma2(acc2[li][3], a2, wb23.y);
                fma2(acc2[li][0], w2, wc01.x); fma2(acc2[li][1], w2, wc01.y);
                fma2(acc2[li][2], w2, wc23.x); fma2(acc2[li][3], w2, wc23.y);
            }
        }
        #pragma unroll
        for (int li=0; li<4; li++)
            #pragma unroll
            for (int j=0; j<4; j++) {
                float2 f = unpack2(acc2[li][j]);
                m_s[(lg*4+li)*304 + j0 + j] = tanhf(fusb[j0+j] + f.x + f.y);
            }
    }
    __syncthreads();
    if (tid < 300) {
        for (int c = 0; c < 4; c++) {
            int grp = c*75 + jg;
            if (grp >= 226) break;
            int jl0 = grp*4;
            int dir = jl0/452, g0 = jl0%452;
            const float* __restrict__ WM = g_mWihT2[dir];
            const float* __restrict__ mb = dir ? mbihb : mbihf;
            ull acc2[4][4];
            #pragma unroll
            for (int li=0; li<4; li++)
                #pragma unroll
                for (int j=0; j<4; j++) acc2[li][j] = 0ull;
            #pragma unroll 2
            for (int d2 = 0; d2 < 150; d2++) {
                int wo = (d2*452 + g0)*2;
                ulonglong2 w01 = *(const ulonglong2*)&WM[wo];
                ulonglong2 w23 = *(const ulonglong2*)&WM[wo+4];
                #pragma unroll
                for (int li = 0; li < 4; li++) {
                    ull mv2 = *(const ull*)&m_s[(lg*4+li)*304 + 2*d2];
                    fma2(acc2[li][0], mv2, w01.x); fma2(acc2[li][1], mv2, w01.y);
                    fma2(acc2[li][2], mv2, w23.x); fma2(acc2[li][3], mv2, w23.y);
                }
            }
            #pragma unroll
            for (int li=0; li<4; li++)
                #pragma unroll
                for (int j=0; j<4; j++)
                    if (g0+j < 450) {
                        float2 f = unpack2(acc2[li][j]);
                        g_xpm[dir][((size_t)(l0+lg*4+li)*320 + n)*450 + g0 + j]
                            = mb[g0+j] + f.x + f.y;
                    }
        }
    }
}

// ------------------------------ match GRU ----------------------------------
__global__ void __launch_bounds__(480) k_mrnn(const float* __restrict__ bhhf,
                                              const float* __restrict__ bhhb) {
    extern __shared__ float sm[];
    float* Wsm = sm;                   // 450 * WPAD_M (thread-major)
    float* hs  = sm + 450*WPAD_M;      // 4*152
    float* hgs = hs + 4*152;           // 4*452
    float* xgs = hgs + 4*452;          // 4*452
    float* rms = xgs + 4*452;          // 4*152
    int dir = blockIdx.x / 80;
    int n0 = (blockIdx.x % 80) * 4;
    const float* __restrict__ WT = g_WhhT[2 + dir];
    const float* __restrict__ bhh = dir ? bhhb : bhhf;
    const float* __restrict__ xp = g_xpm[dir];
    int tid = threadIdx.x;
    for (int i = tid; i < 450*WSM_M; i += blockDim.x) {
        int e = i / 450, g2 = i % 450;
        Wsm[g2*WPAD_M + e] = WT[(WREG_M+e)*450 + g2];
    }
    for (int i = tid; i < 4*152; i += blockDim.x) hs[i] = 0.f;
    int lens[4]; int maxlen = 0;
    #pragma unroll
    for (int ni = 0; ni < 4; ni++) { lens[ni] = g_len[n0+ni]; if (lens[ni] > maxlen) maxlen = lens[ni]; }
    for (int i = tid; i < 4*152; i += blockDim.x) {
        int ni = i/152;
        rms[i] = (lens[ni] < 96) ? 0.f : -1e30f;
    }
    int g = tid;
    ull wreg2[WREG_M/2];
    if (g < 450) {
        #pragma unroll
        for (int e2 = 0; e2 < WREG_M/2; e2++)
            wreg2[e2] = pack2(WT[(2*e2)*450 + g], WT[(2*e2+1)*450 + g]);
    }
    __syncthreads();
    float bias = (g < 450) ? bhh[g] : 0.f;
    const ulonglong2* wv = (const ulonglong2*)(Wsm + g*WPAD_M);
    float xnx[4];
    if (g < 450) {
        #pragma unroll
        for (int ni = 0; ni < 4; ni++) {
            int li = dir ? (lens[ni]-1) : 0;
            if (li < 0) li = 0;
            if (li > 95) li = 95;
            xnx[ni] = xp[((size_t)li*320 + n0 + ni)*450 + g];
        }
    }
    for (int s = 0; s < maxlen; s++) {
        if (g < 450) {
            ull a2a[4], a2b[4];
            #pragma unroll
            for (int ni=0; ni<4; ni++) { a2a[ni] = 0ull; a2b[ni] = 0ull; }
            #pragma unroll
            for (int e = 0; e < WREG_M; e += 4) {
                #pragma unroll
                for (int ni = 0; ni < 4; ni++) {
                    ulonglong2 hv = *(const ulonglong2*)&hs[ni*152 + e];
                    fma2(a2a[ni], hv.x, wreg2[e/2]);
                    fma2(a2b[ni], hv.y, wreg2[e/2+1]);
                }
            }
            #pragma unroll
            for (int e = 0; e < WSM_M; e += 4) {
                ulonglong2 wp = wv[e/4];
                #pragma unroll
                for (int ni = 0; ni < 4; ni++) {
                    ulonglong2 hv = *(const ulonglong2*)&hs[ni*152 + WREG_M + e];
                    fma2(a2a[ni], hv.x, wp.x);
                    fma2(a2b[ni], hv.y, wp.y);
                }
            }
            #pragma unroll
            for (int ni = 0; ni < 4; ni++) {
                float2 fa = unpack2(a2a[ni]), fb = unpack2(a2b[ni]);
                hgs[ni*452+g] = bias + (fa.x+fa.y) + (fb.x+fb.y);
                xgs[ni*452+g] = xnx[ni];
            }
        }
        __syncthreads();
        if (s + 1 < maxlen && g < 450) {
            #pragma unroll
            for (int ni = 0; ni < 4; ni++) {
                int li = dir ? (lens[ni]-2-s) : (s+1);
                if (li < 0) li = 0;
                if (li > 95) li = 95;
                xnx[ni] = xp[((size_t)li*320 + n0 + ni)*450 + g];
            }
        }
        if (g < 150) {
            #pragma unroll
            for (int ni = 0; ni < 4; ni++) {
                float m = (s < lens[ni]) ? 1.f : 0.f;
                float xr = xgs[ni*452+g], xz = xgs[ni*452+g+150], xn = xgs[ni*452+g+300];
                float hr = hgs[ni*452+g], hz = hgs[ni*452+g+150], hn = hgs[ni*452+g+300];
                float rr = 1.f/(1.f+expf(-(xr+hr)));
                float z  = 1.f/(1.f+expf(-(xz+hz)));
                float nn = tanhf(xn + rr*hn);
                float hp = hs[ni*152+g];
                float hnew = (1.f-z)*nn + z*hp;
                float o = m*hnew;
                hs[ni*152+g] = o + (1.f-m)*hp;
                rms[ni*152+g] = fmaxf(rms[ni*152+g], o);
            }
        }
        __syncthreads();
    }
    if (g < 150)
        for (int ni = 0; ni < 4; ni++)
            g_ans[(n0+ni)*300 + dir*150 + g] = rms[ni*152+g];
}

// ------------------------------ output -------------------------------------
__global__ void k_out(const float* __restrict__ outw, const float* __restrict__ outb,
                      float* __restrict__ out) {
    int b = blockIdx.x, w = threadIdx.x >> 5, lane = threadIdx.x & 31;
    __shared__ float lg[10];
    if (w < 10) {
        int n = b*10 + w;
        float s = 0.f;
        for (int d = lane; d < 300; d += 32) s += g_ans[n*300+d] * outw[d];
        for (int o = 16; o; o >>= 1) s += __shfl_xor_sync(0xffffffffu, s, o);
        if (lane == 0) lg[w] = s + outb[0];
    }
    __syncthreads();
    if (threadIdx.x == 0) {
        float mx = -1e30f;
        for (int k = 0; k < 10; k++) mx = fmaxf(mx, lg[k]);
        float ss = 0.f; float e[10];
        for (int k = 0; k < 10; k++) { e[k] = expf(lg[k]-mx); ss += e[k]; }
        for (int k = 0; k < 10; k++) out[b*10+k] = e[k]/ss;
    }
}

// ------------------------------ launch -------------------------------------
extern "C" void kernel_launch(void* const* d_in, const int* in_sizes, int n_in,
                              void* d_out, int out_size) {
    const int*   ctx   = (const int*)d_in[0];
    const int*   ques  = (const int*)d_in[1];
    const int*   ca    = (const int*)d_in[2];
    const float* emb   = (const float*)d_in[3];
    const float* eWihf = (const float*)d_in[4];
    const float* eWhhf = (const float*)d_in[5];
    const float* ebihf = (const float*)d_in[6];
    const float* ebhhf = (const float*)d_in[7];
    const float* eWihb = (const float*)d_in[8];
    const float* eWhhb = (const float*)d_in[9];
    const float* ebihb = (const float*)d_in[10];
    const float* ebhhb = (const float*)d_in[11];
    const float* mWihf = (const float*)d_in[12];
    const float* mWhhf = (const float*)d_in[13];
    const float* mbihf = (const float*)d_in[14];
    const float* mbhhf = (const float*)d_in[15];
    const float* mWihb = (const float*)d_in[16];
    const float* mWhhb = (const float*)d_in[17];
    const float* mbihb = (const float*)d_in[18];
    const float* mbhhb = (const float*)d_in[19];
    const float* fusW  = (const float*)d_in[20];
    const float* fusb  = (const float*)d_in[21];
    const float* outw  = (const float*)d_in[22];
    const float* outb  = (const float*)d_in[23];

    const int SM_ERNN = (480*WPAD_E + 2*152 + 400) * 4;
    const int SM_ATTN = (32*304 + 300*33 + 32*400) * 4;
    const int SM_FUSE = (4*16*304) * 4;
    const int SM_MRNN = (450*WPAD_M + 4*152 + 4*452 + 4*452 + 4*152) * 4;
    cudaFuncSetAttribute(k_ernn, cudaFuncAttributeMaxDynamicSharedMemorySize, SM_ERNN);
    cudaFuncSetAttribute(k_attn, cudaFuncAttributeMaxDynamicSharedMemorySize, SM_ATTN);
    cudaFuncSetAttribute(k_fuse, cudaFuncAttributeMaxDynamicSharedMemorySize, SM_FUSE);
    cudaFuncSetAttribute(k_mrnn, cudaFuncAttributeMaxDynamicSharedMemorySize, SM_MRNN);

    k_prep<<<256, 256>>>(ctx, ques, ca, eWihf, eWihb, eWhhf, eWhhb,
                         mWhhf, mWhhb, mWihf, mWihb, fusW);
    k_xp<<<464, 480>>>(ctx, ques, emb, ebihf, ebihb);
    k_ernn<<<128, 480, SM_ERNN>>>(ebhhf, ebhhb);
    k_attn<<<dim3(320,3), 320, SM_ATTN>>>(ca);
    k_fuse<<<dim3(320,6), 320, SM_FUSE>>>(fusb, mbihf, mbihb);
    k_mrnn<<<160, 480, SM_MRNN>>>(mbhhf, mbhhb);
    k_out<<<32, 320>>>(outw, outb, (float*)d_out);
}

// round 13
// speedup vs baseline: 1.0324x; 1.0324x over previous
#include <cuda_runtime.h>
#include <math.h>

#define WREG_E 72  // ernn: Whh cols in registers (36 packed pairs)
#define WSM_E  80  // ernn: Whh cols in smem (thread-major, padded to 84)
#define WPAD_E 84
#define WREG_M 56  // mrnn: cols in registers (28 packed pairs)
#define WSM_M  96  // mrnn: cols in smem (thread-major, padded to 100)
#define WPAD_M 100
#define NB_M   5   // mrnn candidates per CTA (2*64*5 = 640 -> 128 CTAs, one wave)

typedef unsigned long long ull;

__device__ __forceinline__ void fma2(ull& d, ull a, ull b) {
    asm("fma.rn.f32x2 %0, %1, %2, %0;" : "+l"(d) : "l"(a), "l"(b));
}
__device__ __forceinline__ float2 unpack2(ull v) {
    float2 r; asm("mov.b64 {%0,%1}, %2;" : "=f"(r.x), "=f"(r.y) : "l"(v)); return r;
}
__device__ __forceinline__ ull pack2(float lo, float hi) {
    ull p; asm("mov.b64 %0, {%1,%2};" : "=l"(p) : "f"(lo), "f"(hi)); return p;
}

// ------------------------------ scratch ------------------------------------
__device__ float g_xp[2][2][400*32*480];     // [seq][dir][(t*32+b)*480 + laneidx]
__device__ float g_enc[2][400*32*300];       // [(t*32+b)*300 + dir*150+j]
__device__ float g_qa[320*96*300];
__device__ float g_aw[320*96*300];
__device__ float g_xpm[2][96*320*450];       // [(l*320+n)*450+g]
__device__ float g_ans[320*300];
__device__ float g_WihL2[2][150*480*2];      // paired: [(e2*480+idx)*2+p]
__device__ float g_mWihT2[2][150*452*2];     // paired: [(d2*452+g)*2+p]
__device__ float g_WhhT[4][152*450];         // (slots 2,3 used: matchf,matchb)
__device__ float g_Wlane[2][152*480];        // enc Whh lane order: [e*480 + idx]
__device__ float g_WA2[150*300*2], g_WB2[150*300*2], g_WC2[150*300*2];
__device__ float g_cmask[32*400], g_qmask[32*64];
__device__ int   g_len[320];

// lane mapping: warp w (0..14), lane l (0..29): unit u = w*10 + l/3, gate q = l%3,
// Whh/Wih row = q*150 + u.

// ------------------------------ prep ---------------------------------------
__global__ void k_prep(const int* ctx, const int* ques, const int* ca,
                       const float* eWihf, const float* eWihb,
                       const float* eWhhf, const float* eWhhb,
                       const float* mWhhf, const float* mWhhb,
                       const float* mWihf, const float* mWihb,
                       const float* fusW) {
    int t0 = blockIdx.x*blockDim.x + threadIdx.x;
    int stride = gridDim.x*blockDim.x;
    // lane-ordered + e-paired enc Wih
    for (int i = t0; i < 2*150*480*2; i += stride) {
        int dir = i / (150*480*2);
        int rem = i % (150*480*2);
        int p = rem & 1, t = rem >> 1;
        int e2 = t / 480, idx = t % 480;
        int w = idx >> 5, l = idx & 31;
        float v = 0.f;
        if (l < 30) {
            int u = w*10 + l/3, q = l%3;
            int row = q*150 + u;
            v = (dir ? eWihb : eWihf)[row*300 + 2*e2 + p];
        }
        g_WihL2[dir][rem] = v;
    }
    // paired match Wih (transposed)
    for (int i = t0; i < 2*150*452*2; i += stride) {
        int dir = i / (150*452*2);
        int rem = i % (150*452*2);
        int p = rem & 1, t = rem >> 1;
        int d2 = t / 452, g = t % 452;
        float v = 0.f;
        if (g < 450) v = (dir ? mWihb : mWihf)[g*300 + 2*d2 + p];
        g_mWihT2[dir][rem] = v;
    }
    for (int i = t0; i < 152*450; i += stride) {
        int e = i/450, g = i%450;
        float c=0,d=0;
        if (e < 150) { c=mWhhf[g*150+e]; d=mWhhb[g*150+e]; }
        g_WhhT[2][i]=c; g_WhhT[3][i]=d;
    }
    // lane-ordered enc Whh
    for (int i = t0; i < 2*152*480; i += stride) {
        int dir = i / (152*480);
        int rem = i % (152*480);
        int e = rem / 480, idx = rem % 480;
        int w = idx >> 5, l = idx & 31;
        float v = 0.f;
        if (l < 30 && e < 150) {
            int u = w*10 + l/3, q = l%3;
            int row = q*150 + u;
            v = (dir ? eWhhb : eWhhf)[row*150 + e];
        }
        g_Wlane[dir][rem] = v;
    }
    // paired fusion weights
    for (int i = t0; i < 150*300*2; i += stride) {
        int p = i & 1, t = i >> 1;
        int d2 = t / 300, j = t % 300;
        int d = 2*d2 + p;
        const float* r = fusW + (size_t)j*1200;
        float w4 = r[900+d];
        g_WA2[i] = r[d] + w4;
        g_WB2[i] = r[300+d] - w4;
        g_WC2[i] = r[600+d];
    }
    for (int i = t0; i < 32*400; i += stride) g_cmask[i] = (ctx[i]!=0)?1.f:0.f;
    for (int i = t0; i < 32*64;  i += stride) g_qmask[i] = (ques[i]!=0)?1.f:0.f;
    for (int i = t0; i < 320; i += stride) {
        int bq = i/10;
        int c = 0;
        for (int t = 0; t < 64; t++) c += (ques[bq*64+t] != 0);
        int st = ca[i*2];
        int al = ca[i*2+1] - st;
        int len = al + c;
        if (len > 96) len = 96;
        g_len[i] = len;
    }
}

// ---------------------- encoder input projections --------------------------
// 2 groups of 16 batches to bound register pressure (acc2[16] = 32 regs).
__global__ void __launch_bounds__(480) k_xp(
        const int* __restrict__ ctx, const int* __restrict__ ques,
        const float* __restrict__ emb,
        const float* __restrict__ bihf, const float* __restrict__ bihb) {
    __shared__ float es[32][304];
    __shared__ int tok[32];
    int t = blockIdx.x;
    int seq = (t >= 400) ? 1 : 0;
    int ti = seq ? t-400 : t;
    int T = seq ? 64 : 400;
    const int* toks = seq ? ques : ctx;
    int tid = threadIdx.x;
    if (tid < 32) tok[tid] = toks[tid*T + ti];
    __syncthreads();
    for (int i = tid; i < 32*300; i += blockDim.x) {
        int b=i/300, e=i%300;
        es[b][e] = emb[(size_t)tok[b]*300 + e];
    }
    __syncthreads();
    int w = tid >> 5, l = tid & 31;
    bool active = (l < 30);
    int u = w*10 + l/3, q = l - (l/3)*3;
    int row = q*150 + u;
    for (int dir = 0; dir < 2; dir++) {
        const float* __restrict__ WT = g_WihL2[dir];
        float bias = active ? (dir ? bihb : bihf)[row] : 0.f;
        float* out = g_xp[seq][dir];
        for (int grp = 0; grp < 2; grp++) {
            int bb = grp*16;
            ull acc2[16];
            #pragma unroll
            for (int b=0;b<16;b++) acc2[b] = 0ull;
            for (int e2 = 0; e2 < 150; e2 += 2) {
                ull w2a = *(const ull*)&WT[(e2*480+tid)*2];
                ull w2b = *(const ull*)&WT[((e2+1)*480+tid)*2];
                #pragma unroll
                for (int b=0;b<16;b++) {
                    ulonglong2 v = *(const ulonglong2*)&es[bb+b][2*e2];
                    fma2(acc2[b], v.x, w2a);
                    fma2(acc2[b], v.y, w2b);
                }
            }
            #pragma unroll
            for (int b=0;b<16;b++) {
                float2 f = unpack2(acc2[b]);
                out[((size_t)ti*32+bb+b)*480 + tid] = bias + f.x + f.y;
            }
        }
    }
}

// ---------------------------- encoder GRU ----------------------------------
__global__ void __launch_bounds__(480) k_ernn(const float* __restrict__ bhhf,
                                              const float* __restrict__ bhhb) {
    extern __shared__ float sm[];
    float* Wsm = sm;                   // 480 * WPAD_E (thread-major)
    float* hbuf = sm + 480*WPAD_E;     // 2 * 152 (double buffer)
    float* msm = hbuf + 2*152;         // T masks
    int id = blockIdx.x;
    int seq = (id >= 64) ? 1 : 0;
    int r = seq ? id-64 : id;
    int dir = r >> 5, b = r & 31;
    int T = seq ? 64 : 400;
    const float* __restrict__ WL = g_Wlane[dir];
    const float* __restrict__ bhh = dir ? bhhb : bhhf;
    const float* __restrict__ xp = g_xp[seq][dir];
    float* out = g_enc[seq];
    const float* __restrict__ mask = seq ? g_qmask : g_cmask;
    int tid = threadIdx.x;
    int w = tid >> 5, l = tid & 31;
    bool active = (l < 30);
    int u = w*10 + l/3;
    int q = l - (l/3)*3;
    int row = q*150 + u;

    for (int i = tid; i < 480*WSM_E; i += 480) {
        int j = i / WSM_E, e = i % WSM_E;
        Wsm[j*WPAD_E + e] = WL[(WREG_E+e)*480 + j];
    }
    for (int i = tid; i < 2*152; i += 480) hbuf[i] = 0.f;
    for (int i = tid; i < T; i += 480) msm[i] = mask[b*T + i];
    ull wreg2[WREG_E/2];
    #pragma unroll
    for (int e2 = 0; e2 < WREG_E/2; e2++)
        wreg2[e2] = pack2(WL[(2*e2)*480 + tid], WL[(2*e2+1)*480 + tid]);
    float bias = active ? bhh[row] : 0.f;
    __syncthreads();

    const ulonglong2* wv = (const ulonglong2*)(Wsm + tid*WPAD_E);
    int cur = 0;
    int tt0 = dir ? (T-1) : 0;
    float xnext = xp[((size_t)tt0*32+b)*480 + tid];
    for (int s = 0; s < T; s++) {
        int tt = dir ? (T-1-s) : s;
        float xg = xnext;
        const float* hcur = hbuf + cur*152;
        ull a0 = 0ull, a1 = 0ull, a2 = 0ull, a3 = 0ull;
        #pragma unroll
        for (int e = 0; e < WREG_E; e += 8) {
            ulonglong2 h1 = *(const ulonglong2*)&hcur[e];
            ulonglong2 h2 = *(const ulonglong2*)&hcur[e+4];
            fma2(a0, h1.x, wreg2[e/2]);
            fma2(a1, h1.y, wreg2[e/2+1]);
            fma2(a2, h2.x, wreg2[e/2+2]);
            fma2(a3, h2.y, wreg2[e/2+3]);
        }
        #pragma unroll
        for (int e = 0; e < WSM_E; e += 8) {
            ulonglong2 w1 = wv[e/4];
            ulonglong2 w2 = wv[e/4+1];
            ulonglong2 h1 = *(const ulonglong2*)&hcur[WREG_E+e];
            ulonglong2 h2 = *(const ulonglong2*)&hcur[WREG_E+e+4];
            fma2(a0, h1.x, w1.x);
            fma2(a1, h1.y, w1.y);
            fma2(a2, h2.x, w2.x);
            fma2(a3, h2.y, w2.y);
        }
        float2 f0 = unpack2(a0), f1 = unpack2(a1), f2 = unpack2(a2), f3 = unpack2(a3);
        float hd = bias + ((f0.x+f0.y)+(f1.x+f1.y)) + ((f2.x+f2.y)+(f3.x+f3.y));
        if (s + 1 < T) {
            int tn = dir ? (T-2-s) : (s+1);
            xnext = xp[((size_t)tn*32+b)*480 + tid];
        }
        int base = (l/3)*3;
        float hd_r = __shfl_sync(0xffffffffu, hd, base);
        float hd_z = __shfl_sync(0xffffffffu, hd, base+1);
        float hd_n = __shfl_sync(0xffffffffu, hd, base+2);
        float xg_r = __shfl_sync(0xffffffffu, xg, base);
        float xg_z = __shfl_sync(0xffffffffu, xg, base+1);
        float xg_n = __shfl_sync(0xffffffffu, xg, base+2);
        if (active) {
            float m  = msm[tt];
            float rr = 1.f/(1.f+expf(-(xg_r+hd_r)));
            float z  = 1.f/(1.f+expf(-(xg_z+hd_z)));
            float nn = tanhf(xg_n + rr*hd_n);
            float hp = hcur[u];
            float hnew = (1.f-z)*nn + z*hp;
            float o = m*hnew;
            if (q == 0) {
                hbuf[(cur^1)*152 + u] = o + (1.f-m)*hp;
                out[((size_t)tt*32+b)*300 + dir*150 + u] = o;
            }
        }
        cur ^= 1;
        __syncthreads();
    }
}

// -------------------- attention (with fused qa gather) ----------------------
__global__ void k_attn(const int* __restrict__ ca) {
    extern __shared__ float sm[];
    float* qa_s = sm;              // 32*304
    float* ceT  = sm + 32*304;     // 300*33
    float* sc   = ceT + 300*33;    // 32*400
    int n = blockIdx.x, lt = blockIdx.y, l0 = lt*32;
    int len = g_len[n];
    if (l0 >= len) return;
    int b = n/10;
    int st = ca[n*2], alen = ca[n*2+1] - st;
    int tid = threadIdx.x, warp = tid>>5, lane = tid&31;
    for (int i = tid; i < 32*300; i += 320) {
        int l = i/300, d = i%300;
        int gl = l0 + l;
        float v = 0.f;
        if (gl < len) {
            if (gl < alen) {
                int t = st + gl; if (t > 399) t = 399;
                v = g_enc[0][((size_t)t*32+b)*300 + d];
            } else {
                int t = gl - alen; if (t > 63) t = 63;
                v = g_enc[1][((size_t)t*32+b)*300 + d];
            }
        }
        qa_s[l*304+d] = v;
        g_qa[((size_t)n*96+gl)*300 + d] = v;
    }
    __syncthreads();
    // pass 1: scores
    for (int t0 = 0; t0 < 400; t0 += 32) {
        int tw = (400 - t0 < 32) ? (400 - t0) : 32;
        for (int i = tid; i < 32*300; i += 320) {
            int t = i/300, d = i%300;
            ceT[d*33+t] = (t < tw) ? g_enc[0][((size_t)(t0+t)*32+b)*300 + d] : 0.f;
        }
        __syncthreads();
        if (warp < 8) {
            int t = lane;
            float a0=0.f,a1=0.f,a2=0.f,a3=0.f;
            int L0=warp, L1=warp+8, L2=warp+16, L3=warp+24;
            #pragma unroll 4
            for (int d = 0; d < 300; d += 4) {
                float c0=ceT[d*33+t], c1=ceT[(d+1)*33+t], c2=ceT[(d+2)*33+t], c3=ceT[(d+3)*33+t];
                float4 qv;
                qv = *(float4*)&qa_s[L0*304+d]; a0 += qv.x*c0+qv.y*c1+qv.z*c2+qv.w*c3;
                qv = *(float4*)&qa_s[L1*304+d]; a1 += qv.x*c0+qv.y*c1+qv.z*c2+qv.w*c3;
                qv = *(float4*)&qa_s[L2*304+d]; a2 += qv.x*c0+qv.y*c1+qv.z*c2+qv.w*c3;
                qv = *(float4*)&qa_s[L3*304+d]; a3 += qv.x*c0+qv.y*c1+qv.z*c2+qv.w*c3;
            }
            if (t < tw) {
                float cm = g_cmask[b*400 + t0 + t];
                float big = -1e30f;
                sc[L0*400+t0+t] = cm>0.f ? a0 : big;
                sc[L1*400+t0+t] = cm>0.f ? a1 : big;
                sc[L2*400+t0+t] = cm>0.f ? a2 : big;
                sc[L3*400+t0+t] = cm>0.f ? a3 : big;
            }
        }
        __syncthreads();
    }
    // softmax per row
    for (int l = warp; l < 32; l += 10) {
        float mx = -1e30f;
        for (int t = lane; t < 400; t += 32) mx = fmaxf(mx, sc[l*400+t]);
        for (int o = 16; o; o >>= 1) mx = fmaxf(mx, __shfl_xor_sync(0xffffffffu, mx, o));
        float ss = 0.f;
        for (int t = lane; t < 400; t += 32) { float e = expf(sc[l*400+t]-mx); sc[l*400+t]=e; ss += e; }
        for (int o = 16; o; o >>= 1) ss += __shfl_xor_sync(0xffffffffu, ss, o);
        float inv = 1.f/ss;
        for (int t = lane; t < 400; t += 32) sc[l*400+t] *= inv;
    }
    __syncthreads();
    // pass 2: aware
    int d = tid;
    float acc[32];
    #pragma unroll
    for (int l = 0; l < 32; l++) acc[l] = 0.f;
    for (int t0 = 0; t0 < 400; t0 += 32) {
        int tw = (400 - t0 < 32) ? (400 - t0) : 32;
        for (int i = tid; i < 32*300; i += 320) {
            int t = i/300, dd = i%300;
            ceT[dd*33+t] = (t < tw) ? g_enc[0][((size_t)(t0+t)*32+b)*300 + dd] : 0.f;
        }
        __syncthreads();
        if (d < 300) {
            for (int t = 0; t < tw; t += 4) {
                float c0=ceT[d*33+t], c1=ceT[d*33+t+1], c2=ceT[d*33+t+2], c3=ceT[d*33+t+3];
                #pragma unroll
                for (int l = 0; l < 32; l++) {
                    float4 al = *(float4*)&sc[l*400 + t0 + t];
                    acc[l] += al.x*c0 + al.y*c1 + al.z*c2 + al.w*c3;
                }
            }
        }
        __syncthreads();
    }
    if (d < 300)
        for (int l = 0; l < 32; l++)
            g_aw[((size_t)n*96 + l0 + l)*300 + d] = acc[l];
}

// ------------------- fusion GEMM + match input projection ------------------
__global__ void __launch_bounds__(320) k_fuse(const float* __restrict__ fusb,
                       const float* __restrict__ mbihf, const float* __restrict__ mbihb) {
    extern __shared__ float sm[];
    float* qa_s = sm;               // 16*304
    float* aw_s = sm + 16*304;
    float* qw_s = aw_s + 16*304;
    float* m_s  = qw_s + 16*304;
    int n = blockIdx.x, lt = blockIdx.y, l0 = lt*16;
    if (l0 >= g_len[n]) return;
    int tid = threadIdx.x;
    for (int i = tid; i < 16*300; i += blockDim.x) {
        int l = i/300, d = i%300;
        float q = g_qa[((size_t)n*96 + l0 + l)*300 + d];
        float a = g_aw[((size_t)n*96 + l0 + l)*300 + d];
        qa_s[l*304+d] = q; aw_s[l*304+d] = a; qw_s[l*304+d] = q*a;
    }
    __syncthreads();
    int lg = tid/75, jg = tid%75, j0 = jg*4;
    if (tid < 300) {
        ull acc2[4][4];
        #pragma unroll
        for (int li=0; li<4; li++)
            #pragma unroll
            for (int j=0; j<4; j++) acc2[li][j] = 0ull;
        #pragma unroll 2
        for (int d2 = 0; d2 < 150; d2++) {
            int wo = (d2*300 + j0)*2;
            ulonglong2 wa01 = *(const ulonglong2*)&g_WA2[wo];
            ulonglong2 wa23 = *(const ulonglong2*)&g_WA2[wo+4];
            ulonglong2 wb01 = *(const ulonglong2*)&g_WB2[wo];
            ulonglong2 wb23 = *(const ulonglong2*)&g_WB2[wo+4];
            ulonglong2 wc01 = *(const ulonglong2*)&g_WC2[wo];
            ulonglong2 wc23 = *(const ulonglong2*)&g_WC2[wo+4];
            #pragma unroll
            for (int li = 0; li < 4; li++) {
                int l = lg*4 + li;
                ull q2 = *(const ull*)&qa_s[l*304 + 2*d2];
                ull a2 = *(const ull*)&aw_s[l*304 + 2*d2];
                ull w2 = *(const ull*)&qw_s[l*304 + 2*d2];
                fma2(acc2[li][0], q2, wa01.x); fma2(acc2[li][1], q2, wa01.y);
                fma2(acc2[li][2], q2, wa23.x); fma2(acc2[li][3], q2, wa23.y);
                fma2(acc2[li][0], a2, wb01.x); fma2(acc2[li][1], a2, wb01.y);
                fma2(acc2[li][2], a2, wb23.x); fma2(acc2[li][3], a2, wb23.y);
                fma2(acc2[li][0], w2, wc01.x); fma2(acc2[li][1], w2, wc01.y);
                fma2(acc2[li][2], w2, wc23.x); fma2(acc2[li][3], w2, wc23.y);
            }
        }
        #pragma unroll
        for (int li=0; li<4; li++)
            #pragma unroll
            for (int j=0; j<4; j++) {
                float2 f = unpack2(acc2[li][j]);
                m_s[(lg*4+li)*304 + j0 + j] = tanhf(fusb[j0+j] + f.x + f.y);
            }
    }
    __syncthreads();
    if (tid < 300) {
        for (int c = 0; c < 4; c++) {
            int grp = c*75 + jg;
            if (grp >= 226) break;
            int jl0 = grp*4;
            int dir = jl0/452, g0 = jl0%452;
            const float* __restrict__ WM = g_mWihT2[dir];
            const float* __restrict__ mb = dir ? mbihb : mbihf;
            ull acc2[4][4];
            #pragma unroll
            for (int li=0; li<4; li++)
                #pragma unroll
                for (int j=0; j<4; j++) acc2[li][j] = 0ull;
            #pragma unroll 2
            for (int d2 = 0; d2 < 150; d2++) {
                int wo = (d2*452 + g0)*2;
                ulonglong2 w01 = *(const ulonglong2*)&WM[wo];
                ulonglong2 w23 = *(const ulonglong2*)&WM[wo+4];
                #pragma unroll
                for (int li = 0; li < 4; li++) {
                    ull mv2 = *(const ull*)&m_s[(lg*4+li)*304 + 2*d2];
                    fma2(acc2[li][0], mv2, w01.x); fma2(acc2[li][1], mv2, w01.y);
                    fma2(acc2[li][2], mv2, w23.x); fma2(acc2[li][3], mv2, w23.y);
                }
            }
            #pragma unroll
            for (int li=0; li<4; li++)
                #pragma unroll
                for (int j=0; j<4; j++)
                    if (g0+j < 450) {
                        float2 f = unpack2(acc2[li][j]);
                        g_xpm[dir][((size_t)(l0+lg*4+li)*320 + n)*450 + g0 + j]
                            = mb[g0+j] + f.x + f.y;
                    }
        }
    }
}

// ------------------------------ match GRU ----------------------------------
// NB_M=5 candidates per CTA -> 128 CTAs = one full wave (was 160 -> 2 waves).
__global__ void __launch_bounds__(480) k_mrnn(const float* __restrict__ bhhf,
                                              const float* __restrict__ bhhb) {
    extern __shared__ float sm[];
    float* Wsm = sm;                      // 450 * WPAD_M (thread-major)
    float* hs  = sm + 450*WPAD_M;         // NB_M*152
    float* hgs = hs + NB_M*152;           // NB_M*452
    float* xgs = hgs + NB_M*452;          // NB_M*452
    float* rms = xgs + NB_M*452;          // NB_M*152
    int dir = blockIdx.x / 64;
    int n0 = (blockIdx.x % 64) * NB_M;
    const float* __restrict__ WT = g_WhhT[2 + dir];
    const float* __restrict__ bhh = dir ? bhhb : bhhf;
    const float* __restrict__ xp = g_xpm[dir];
    int tid = threadIdx.x;
    for (int i = tid; i < 450*WSM_M; i += blockDim.x) {
        int e = i / 450, g2 = i % 450;
        Wsm[g2*WPAD_M + e] = WT[(WREG_M+e)*450 + g2];
    }
    for (int i = tid; i < NB_M*152; i += blockDim.x) hs[i] = 0.f;
    int lens[NB_M]; int maxlen = 0;
    #pragma unroll
    for (int ni = 0; ni < NB_M; ni++) { lens[ni] = g_len[n0+ni]; if (lens[ni] > maxlen) maxlen = lens[ni]; }
    for (int i = tid; i < NB_M*152; i += blockDim.x) {
        int ni = i/152;
        rms[i] = (lens[ni] < 96) ? 0.f : -1e30f;
    }
    int g = tid;
    ull wreg2[WREG_M/2];
    if (g < 450) {
        #pragma unroll
        for (int e2 = 0; e2 < WREG_M/2; e2++)
            wreg2[e2] = pack2(WT[(2*e2)*450 + g], WT[(2*e2+1)*450 + g]);
    }
    __syncthreads();
    float bias = (g < 450) ? bhh[g] : 0.f;
    const ulonglong2* wv = (const ulonglong2*)(Wsm + g*WPAD_M);
    float xnx[NB_M];
    if (g < 450) {
        #pragma unroll
        for (int ni = 0; ni < NB_M; ni++) {
            int li = dir ? (lens[ni]-1) : 0;
            if (li < 0) li = 0;
            if (li > 95) li = 95;
            xnx[ni] = xp[((size_t)li*320 + n0 + ni)*450 + g];
        }
    }
    for (int s = 0; s < maxlen; s++) {
        if (g < 450) {
            ull a2a[NB_M], a2b[NB_M];
            #pragma unroll
            for (int ni=0; ni<NB_M; ni++) { a2a[ni] = 0ull; a2b[ni] = 0ull; }
            #pragma unroll
            for (int e = 0; e < WREG_M; e += 4) {
                #pragma unroll
                for (int ni = 0; ni < NB_M; ni++) {
                    ulonglong2 hv = *(const ulonglong2*)&hs[ni*152 + e];
                    fma2(a2a[ni], hv.x, wreg2[e/2]);
                    fma2(a2b[ni], hv.y, wreg2[e/2+1]);
                }
            }
            #pragma unroll
            for (int e = 0; e < WSM_M; e += 4) {
                ulonglong2 wp = wv[e/4];
                #pragma unroll
                for (int ni = 0; ni < NB_M; ni++) {
                    ulonglong2 hv = *(const ulonglong2*)&hs[ni*152 + WREG_M + e];
                    fma2(a2a[ni], hv.x, wp.x);
                    fma2(a2b[ni], hv.y, wp.y);
                }
            }
            #pragma unroll
            for (int ni = 0; ni < NB_M; ni++) {
                float2 fa = unpack2(a2a[ni]), fb = unpack2(a2b[ni]);
                hgs[ni*452+g] = bias + (fa.x+fa.y) + (fb.x+fb.y);
                xgs[ni*452+g] = xnx[ni];
            }
        }
        __syncthreads();
        if (s + 1 < maxlen && g < 450) {
            #pragma unroll
            for (int ni = 0; ni < NB_M; ni++) {
                int li = dir ? (lens[ni]-2-s) : (s+1);
                if (li < 0) li = 0;
                if (li > 95) li = 95;
                xnx[ni] = xp[((size_t)li*320 + n0 + ni)*450 + g];
            }
        }
        if (g < 150) {
            #pragma unroll
            for (int ni = 0; ni < NB_M; ni++) {
                float m = (s < lens[ni]) ? 1.f : 0.f;
                float xr = xgs[ni*452+g], xz = xgs[ni*452+g+150], xn = xgs[ni*452+g+300];
                float hr = hgs[ni*452+g], hz = hgs[ni*452+g+150], hn = hgs[ni*452+g+300];
                float rr = 1.f/(1.f+expf(-(xr+hr)));
                float z  = 1.f/(1.f+expf(-(xz+hz)));
                float nn = tanhf(xn + rr*hn);
                float hp = hs[ni*152+g];
                float hnew = (1.f-z)*nn + z*hp;
                float o = m*hnew;
                hs[ni*152+g] = o + (1.f-m)*hp;
                rms[ni*152+g] = fmaxf(rms[ni*152+g], o);
            }
        }
        __syncthreads();
    }
    if (g < 150)
        for (int ni = 0; ni < NB_M; ni++)
            g_ans[(n0+ni)*300 + dir*150 + g] = rms[ni*152+g];
}

// ------------------------------ output -------------------------------------
__global__ void k_out(const float* __restrict__ outw, const float* __restrict__ outb,
                      float* __restrict__ out) {
    int b = blockIdx.x, w = threadIdx.x >> 5, lane = threadIdx.x & 31;
    __shared__ float lg[10];
    if (w < 10) {
        int n = b*10 + w;
        float s = 0.f;
        for (int d = lane; d < 300; d += 32) s += g_ans[n*300+d] * outw[d];
        for (int o = 16; o; o >>= 1) s += __shfl_xor_sync(0xffffffffu, s, o);
        if (lane == 0) lg[w] = s + outb[0];
    }
    __syncthreads();
    if (threadIdx.x == 0) {
        float mx = -1e30f;
        for (int k = 0; k < 10; k++) mx = fmaxf(mx, lg[k]);
        float ss = 0.f; float e[10];
        for (int k = 0; k < 10; k++) { e[k] = expf(lg[k]-mx); ss += e[k]; }
        for (int k = 0; k < 10; k++) out[b*10+k] = e[k]/ss;
    }
}

// ------------------------------ launch -------------------------------------
extern "C" void kernel_launch(void* const* d_in, const int* in_sizes, int n_in,
                              void* d_out, int out_size) {
    const int*   ctx   = (const int*)d_in[0];
    const int*   ques  = (const int*)d_in[1];
    const int*   ca    = (const int*)d_in[2];
    const float* emb   = (const float*)d_in[3];
    const float* eWihf = (const float*)d_in[4];
    const float* eWhhf = (const float*)d_in[5];
    const float* ebihf = (const float*)d_in[6];
    const float* ebhhf = (const float*)d_in[7];
    const float* eWihb = (const float*)d_in[8];
    const float* eWhhb = (const float*)d_in[9];
    const float* ebihb = (const float*)d_in[10];
    const float* ebhhb = (const float*)d_in[11];
    const float* mWihf = (const float*)d_in[12];
    const float* mWhhf = (const float*)d_in[13];
    const float* mbihf = (const float*)d_in[14];
    const float* mbhhf = (const float*)d_in[15];
    const float* mWihb = (const float*)d_in[16];
    const float* mWhhb = (const float*)d_in[17];
    const float* mbihb = (const float*)d_in[18];
    const float* mbhhb = (const float*)d_in[19];
    const float* fusW  = (const float*)d_in[20];
    const float* fusb  = (const float*)d_in[21];
    const float* outw  = (const float*)d_in[22];
    const float* outb  = (const float*)d_in[23];

    const int SM_ERNN = (480*WPAD_E + 2*152 + 400) * 4;
    const int SM_ATTN = (32*304 + 300*33 + 32*400) * 4;
    const int SM_FUSE = (4*16*304) * 4;
    const int SM_MRNN = (450*WPAD_M + NB_M*152 + NB_M*452 + NB_M*452 + NB_M*152) * 4;
    cudaFuncSetAttribute(k_ernn, cudaFuncAttributeMaxDynamicSharedMemorySize, SM_ERNN);
    cudaFuncSetAttribute(k_attn, cudaFuncAttributeMaxDynamicSharedMemorySize, SM_ATTN);
    cudaFuncSetAttribute(k_fuse, cudaFuncAttributeMaxDynamicSharedMemorySize, SM_FUSE);
    cudaFuncSetAttribute(k_mrnn, cudaFuncAttributeMaxDynamicSharedMemorySize, SM_MRNN);

    k_prep<<<256, 256>>>(ctx, ques, ca, eWihf, eWihb, eWhhf, eWhhb,
                         mWhhf, mWhhb, mWihf, mWihb, fusW);
    k_xp<<<464, 480>>>(ctx, ques, emb, ebihf, ebihb);
    k_ernn<<<128, 480, SM_ERNN>>>(ebhhf, ebhhb);
    k_attn<<<dim3(320,3), 320, SM_ATTN>>>(ca);
    k_fuse<<<dim3(320,6), 320, SM_FUSE>>>(fusb, mbihf, mbihb);
    k_mrnn<<<128, 480, SM_MRNN>>>(mbhhf, mbhhb);
    k_out<<<32, 320>>>(outw, outb, (float*)d_out);
}

// round 14
// speedup vs baseline: 1.0581x; 1.0249x over previous
#include <cuda_runtime.h>
#include <math.h>

#define WREG_E 72  // ernn: Whh cols in registers (36 packed pairs)
#define WSM_E  80  // ernn: Whh cols in smem (thread-major, padded to 84)
#define WPAD_E 84
#define WREG_M 56  // mrnn: cols in registers (28 packed pairs)
#define WSM_M  96  // mrnn: cols in smem (thread-major, padded to 100)
#define WPAD_M 100
#define NB_M   5   // mrnn candidates per CTA (2*64*5 = 640 -> 128 CTAs, one wave)

typedef unsigned long long ull;

__device__ __forceinline__ void fma2(ull& d, ull a, ull b) {
    asm("fma.rn.f32x2 %0, %1, %2, %0;" : "+l"(d) : "l"(a), "l"(b));
}
__device__ __forceinline__ float2 unpack2(ull v) {
    float2 r; asm("mov.b64 {%0,%1}, %2;" : "=f"(r.x), "=f"(r.y) : "l"(v)); return r;
}
__device__ __forceinline__ ull pack2(float lo, float hi) {
    ull p; asm("mov.b64 %0, {%1,%2};" : "=l"(p) : "f"(lo), "f"(hi)); return p;
}

// ------------------------------ scratch ------------------------------------
__device__ float g_xp[2][2][400*32*480];     // [seq][dir][(t*32+b)*480 + laneidx]
__device__ float g_enc[2][400*32*300];       // [(t*32+b)*300 + dir*150+j]
__device__ float g_qa[320*96*300];
__device__ float g_aw[320*96*300];
__device__ float g_xpm[2][96*320*450];       // [(l*320+n)*450+g]
__device__ float g_ans[320*300];
__device__ float g_WihL2[2][150*480*2];      // paired: [(e2*480+idx)*2+p]
__device__ float g_mWihT2[2][150*452*2];     // paired: [(d2*452+g)*2+p]
__device__ float g_WhhT[4][152*450];         // (slots 2,3 used: matchf,matchb)
__device__ float g_Wlane[2][152*480];        // enc Whh lane order: [e*480 + idx]
__device__ float g_WA2[150*300*2], g_WB2[150*300*2], g_WC2[150*300*2];
__device__ float g_cmask[32*400], g_qmask[32*64];
__device__ int   g_len[320];

// lane mapping: warp w (0..14), lane l (0..29): unit u = w*10 + l/3, gate q = l%3,
// Whh/Wih row = q*150 + u.

// ------------------------------ prep ---------------------------------------
__global__ void k_prep(const int* ctx, const int* ques, const int* ca,
                       const float* eWihf, const float* eWihb,
                       const float* eWhhf, const float* eWhhb,
                       const float* mWhhf, const float* mWhhb,
                       const float* mWihf, const float* mWihb,
                       const float* fusW) {
    int t0 = blockIdx.x*blockDim.x + threadIdx.x;
    int stride = gridDim.x*blockDim.x;
    // lane-ordered + e-paired enc Wih
    for (int i = t0; i < 2*150*480*2; i += stride) {
        int dir = i / (150*480*2);
        int rem = i % (150*480*2);
        int p = rem & 1, t = rem >> 1;
        int e2 = t / 480, idx = t % 480;
        int w = idx >> 5, l = idx & 31;
        float v = 0.f;
        if (l < 30) {
            int u = w*10 + l/3, q = l%3;
            int row = q*150 + u;
            v = (dir ? eWihb : eWihf)[row*300 + 2*e2 + p];
        }
        g_WihL2[dir][rem] = v;
    }
    // paired match Wih (transposed)
    for (int i = t0; i < 2*150*452*2; i += stride) {
        int dir = i / (150*452*2);
        int rem = i % (150*452*2);
        int p = rem & 1, t = rem >> 1;
        int d2 = t / 452, g = t % 452;
        float v = 0.f;
        if (g < 450) v = (dir ? mWihb : mWihf)[g*300 + 2*d2 + p];
        g_mWihT2[dir][rem] = v;
    }
    for (int i = t0; i < 152*450; i += stride) {
        int e = i/450, g = i%450;
        float c=0,d=0;
        if (e < 150) { c=mWhhf[g*150+e]; d=mWhhb[g*150+e]; }
        g_WhhT[2][i]=c; g_WhhT[3][i]=d;
    }
    // lane-ordered enc Whh
    for (int i = t0; i < 2*152*480; i += stride) {
        int dir = i / (152*480);
        int rem = i % (152*480);
        int e = rem / 480, idx = rem % 480;
        int w = idx >> 5, l = idx & 31;
        float v = 0.f;
        if (l < 30 && e < 150) {
            int u = w*10 + l/3, q = l%3;
            int row = q*150 + u;
            v = (dir ? eWhhb : eWhhf)[row*150 + e];
        }
        g_Wlane[dir][rem] = v;
    }
    // paired fusion weights
    for (int i = t0; i < 150*300*2; i += stride) {
        int p = i & 1, t = i >> 1;
        int d2 = t / 300, j = t % 300;
        int d = 2*d2 + p;
        const float* r = fusW + (size_t)j*1200;
        float w4 = r[900+d];
        g_WA2[i] = r[d] + w4;
        g_WB2[i] = r[300+d] - w4;
        g_WC2[i] = r[600+d];
    }
    for (int i = t0; i < 32*400; i += stride) g_cmask[i] = (ctx[i]!=0)?1.f:0.f;
    for (int i = t0; i < 32*64;  i += stride) g_qmask[i] = (ques[i]!=0)?1.f:0.f;
    for (int i = t0; i < 320; i += stride) {
        int bq = i/10;
        int c = 0;
        for (int t = 0; t < 64; t++) c += (ques[bq*64+t] != 0);
        int st = ca[i*2];
        int al = ca[i*2+1] - st;
        int len = al + c;
        if (len > 96) len = 96;
        g_len[i] = len;
    }
}

// ---------------------- encoder input projections --------------------------
// 2 groups of 16 batches to bound register pressure (acc2[16] = 32 regs).
__global__ void __launch_bounds__(480) k_xp(
        const int* __restrict__ ctx, const int* __restrict__ ques,
        const float* __restrict__ emb,
        const float* __restrict__ bihf, const float* __restrict__ bihb) {
    __shared__ float es[32][304];
    __shared__ int tok[32];
    int t = blockIdx.x;
    int seq = (t >= 400) ? 1 : 0;
    int ti = seq ? t-400 : t;
    int T = seq ? 64 : 400;
    const int* toks = seq ? ques : ctx;
    int tid = threadIdx.x;
    if (tid < 32) tok[tid] = toks[tid*T + ti];
    __syncthreads();
    for (int i = tid; i < 32*300; i += blockDim.x) {
        int b=i/300, e=i%300;
        es[b][e] = emb[(size_t)tok[b]*300 + e];
    }
    __syncthreads();
    int w = tid >> 5, l = tid & 31;
    bool active = (l < 30);
    int u = w*10 + l/3, q = l - (l/3)*3;
    int row = q*150 + u;
    for (int dir = 0; dir < 2; dir++) {
        const float* __restrict__ WT = g_WihL2[dir];
        float bias = active ? (dir ? bihb : bihf)[row] : 0.f;
        float* out = g_xp[seq][dir];
        for (int grp = 0; grp < 2; grp++) {
            int bb = grp*16;
            ull acc2[16];
            #pragma unroll
            for (int b=0;b<16;b++) acc2[b] = 0ull;
            for (int e2 = 0; e2 < 150; e2 += 2) {
                ull w2a = *(const ull*)&WT[(e2*480+tid)*2];
                ull w2b = *(const ull*)&WT[((e2+1)*480+tid)*2];
                #pragma unroll
                for (int b=0;b<16;b++) {
                    ulonglong2 v = *(const ulonglong2*)&es[bb+b][2*e2];
                    fma2(acc2[b], v.x, w2a);
                    fma2(acc2[b], v.y, w2b);
                }
            }
            #pragma unroll
            for (int b=0;b<16;b++) {
                float2 f = unpack2(acc2[b]);
                out[((size_t)ti*32+bb+b)*480 + tid] = bias + f.x + f.y;
            }
        }
    }
}

// ---------------------------- encoder GRU ----------------------------------
__global__ void __launch_bounds__(480) k_ernn(const float* __restrict__ bhhf,
                                              const float* __restrict__ bhhb) {
    extern __shared__ float sm[];
    float* Wsm = sm;                   // 480 * WPAD_E (thread-major)
    float* hbuf = sm + 480*WPAD_E;     // 2 * 152 (double buffer)
    float* msm = hbuf + 2*152;         // T masks
    int id = blockIdx.x;
    int seq = (id >= 64) ? 1 : 0;
    int r = seq ? id-64 : id;
    int dir = r >> 5, b = r & 31;
    int T = seq ? 64 : 400;
    const float* __restrict__ WL = g_Wlane[dir];
    const float* __restrict__ bhh = dir ? bhhb : bhhf;
    const float* __restrict__ xp = g_xp[seq][dir];
    float* out = g_enc[seq];
    const float* __restrict__ mask = seq ? g_qmask : g_cmask;
    int tid = threadIdx.x;
    int w = tid >> 5, l = tid & 31;
    bool active = (l < 30);
    int u = w*10 + l/3;
    int q = l - (l/3)*3;
    int row = q*150 + u;

    for (int i = tid; i < 480*WSM_E; i += 480) {
        int j = i / WSM_E, e = i % WSM_E;
        Wsm[j*WPAD_E + e] = WL[(WREG_E+e)*480 + j];
    }
    for (int i = tid; i < 2*152; i += 480) hbuf[i] = 0.f;
    for (int i = tid; i < T; i += 480) msm[i] = mask[b*T + i];
    ull wreg2[WREG_E/2];
    #pragma unroll
    for (int e2 = 0; e2 < WREG_E/2; e2++)
        wreg2[e2] = pack2(WL[(2*e2)*480 + tid], WL[(2*e2+1)*480 + tid]);
    float bias = active ? bhh[row] : 0.f;
    __syncthreads();

    const ulonglong2* wv = (const ulonglong2*)(Wsm + tid*WPAD_E);
    int cur = 0;
    int tt0 = dir ? (T-1) : 0;
    float xnext = xp[((size_t)tt0*32+b)*480 + tid];
    for (int s = 0; s < T; s++) {
        int tt = dir ? (T-1-s) : s;
        float xg = xnext;
        const float* hcur = hbuf + cur*152;
        ull a0 = 0ull, a1 = 0ull, a2 = 0ull, a3 = 0ull;
        #pragma unroll
        for (int e = 0; e < WREG_E; e += 8) {
            ulonglong2 h1 = *(const ulonglong2*)&hcur[e];
            ulonglong2 h2 = *(const ulonglong2*)&hcur[e+4];
            fma2(a0, h1.x, wreg2[e/2]);
            fma2(a1, h1.y, wreg2[e/2+1]);
            fma2(a2, h2.x, wreg2[e/2+2]);
            fma2(a3, h2.y, wreg2[e/2+3]);
        }
        #pragma unroll
        for (int e = 0; e < WSM_E; e += 8) {
            ulonglong2 w1 = wv[e/4];
            ulonglong2 w2 = wv[e/4+1];
            ulonglong2 h1 = *(const ulonglong2*)&hcur[WREG_E+e];
            ulonglong2 h2 = *(const ulonglong2*)&hcur[WREG_E+e+4];
            fma2(a0, h1.x, w1.x);
            fma2(a1, h1.y, w1.y);
            fma2(a2, h2.x, w2.x);
            fma2(a3, h2.y, w2.y);
        }
        float2 f0 = unpack2(a0), f1 = unpack2(a1), f2 = unpack2(a2), f3 = unpack2(a3);
        float hd = bias + ((f0.x+f0.y)+(f1.x+f1.y)) + ((f2.x+f2.y)+(f3.x+f3.y));
        if (s + 1 < T) {
            int tn = dir ? (T-2-s) : (s+1);
            xnext = xp[((size_t)tn*32+b)*480 + tid];
        }
        int base = (l/3)*3;
        float hd_r = __shfl_sync(0xffffffffu, hd, base);
        float hd_z = __shfl_sync(0xffffffffu, hd, base+1);
        float hd_n = __shfl_sync(0xffffffffu, hd, base+2);
        float xg_r = __shfl_sync(0xffffffffu, xg, base);
        float xg_z = __shfl_sync(0xffffffffu, xg, base+1);
        float xg_n = __shfl_sync(0xffffffffu, xg, base+2);
        if (active) {
            float m  = msm[tt];
            float rr = 1.f/(1.f+expf(-(xg_r+hd_r)));
            float z  = 1.f/(1.f+expf(-(xg_z+hd_z)));
            float nn = tanhf(xg_n + rr*hd_n);
            float hp = hcur[u];
            float hnew = (1.f-z)*nn + z*hp;
            float o = m*hnew;
            if (q == 0) {
                hbuf[(cur^1)*152 + u] = o + (1.f-m)*hp;
                out[((size_t)tt*32+b)*300 + dir*150 + u] = o;
            }
        }
        cur ^= 1;
        __syncthreads();
    }
}

// -------------------- attention (16-l tiles, 2 CTAs/SM) ---------------------
__global__ void __launch_bounds__(320) k_attn(const int* __restrict__ ca) {
    extern __shared__ float sm[];
    float* qa_s = sm;              // 16*304
    float* ceT  = sm + 16*304;     // 300*33
    float* sc   = ceT + 300*33;    // 16*400
    int n = blockIdx.x, lt = blockIdx.y, l0 = lt*16;
    int len = g_len[n];
    if (l0 >= len) return;
    int b = n/10;
    int st = ca[n*2], alen = ca[n*2+1] - st;
    int tid = threadIdx.x, warp = tid>>5, lane = tid&31;
    // gather qa tile (and persist to g_qa for k_fuse)
    for (int i = tid; i < 16*300; i += 320) {
        int l = i/300, d = i%300;
        int gl = l0 + l;
        float v = 0.f;
        if (gl < len) {
            if (gl < alen) {
                int t = st + gl; if (t > 399) t = 399;
                v = g_enc[0][((size_t)t*32+b)*300 + d];
            } else {
                int t = gl - alen; if (t > 63) t = 63;
                v = g_enc[1][((size_t)t*32+b)*300 + d];
            }
        }
        qa_s[l*304+d] = v;
        g_qa[((size_t)n*96+gl)*300 + d] = v;
    }
    __syncthreads();
    // pass 1: scores (warps 0-7, rows warp and warp+8, t = lane)
    for (int t0 = 0; t0 < 400; t0 += 32) {
        int tw = (400 - t0 < 32) ? (400 - t0) : 32;
        for (int i = tid; i < 32*300; i += 320) {
            int t = i/300, d = i%300;
            ceT[d*33+t] = (t < tw) ? g_enc[0][((size_t)(t0+t)*32+b)*300 + d] : 0.f;
        }
        __syncthreads();
        if (warp < 8) {
            int t = lane;
            float a0=0.f,a1=0.f;
            int L0=warp, L1=warp+8;
            #pragma unroll 4
            for (int d = 0; d < 300; d += 4) {
                float c0=ceT[d*33+t], c1=ceT[(d+1)*33+t], c2=ceT[(d+2)*33+t], c3=ceT[(d+3)*33+t];
                float4 qv;
                qv = *(float4*)&qa_s[L0*304+d]; a0 += qv.x*c0+qv.y*c1+qv.z*c2+qv.w*c3;
                qv = *(float4*)&qa_s[L1*304+d]; a1 += qv.x*c0+qv.y*c1+qv.z*c2+qv.w*c3;
            }
            if (t < tw) {
                float cm = g_cmask[b*400 + t0 + t];
                float big = -1e30f;
                sc[L0*400+t0+t] = cm>0.f ? a0 : big;
                sc[L1*400+t0+t] = cm>0.f ? a1 : big;
            }
        }
        __syncthreads();
    }
    // softmax per row
    for (int l = warp; l < 16; l += 10) {
        float mx = -1e30f;
        for (int t = lane; t < 400; t += 32) mx = fmaxf(mx, sc[l*400+t]);
        for (int o = 16; o; o >>= 1) mx = fmaxf(mx, __shfl_xor_sync(0xffffffffu, mx, o));
        float ss = 0.f;
        for (int t = lane; t < 400; t += 32) { float e = expf(sc[l*400+t]-mx); sc[l*400+t]=e; ss += e; }
        for (int o = 16; o; o >>= 1) ss += __shfl_xor_sync(0xffffffffu, ss, o);
        float inv = 1.f/ss;
        for (int t = lane; t < 400; t += 32) sc[l*400+t] *= inv;
    }
    __syncthreads();
    // pass 2: aware
    int d = tid;
    float acc[16];
    #pragma unroll
    for (int l = 0; l < 16; l++) acc[l] = 0.f;
    for (int t0 = 0; t0 < 400; t0 += 32) {
        int tw = (400 - t0 < 32) ? (400 - t0) : 32;
        for (int i = tid; i < 32*300; i += 320) {
            int t = i/300, dd = i%300;
            ceT[dd*33+t] = (t < tw) ? g_enc[0][((size_t)(t0+t)*32+b)*300 + dd] : 0.f;
        }
        __syncthreads();
        if (d < 300) {
            for (int t = 0; t < tw; t += 4) {
                float c0=ceT[d*33+t], c1=ceT[d*33+t+1], c2=ceT[d*33+t+2], c3=ceT[d*33+t+3];
                #pragma unroll
                for (int l = 0; l < 16; l++) {
                    float4 al = *(float4*)&sc[l*400 + t0 + t];
                    acc[l] += al.x*c0 + al.y*c1 + al.z*c2 + al.w*c3;
                }
            }
        }
        __syncthreads();
    }
    if (d < 300)
        for (int l = 0; l < 16; l++)
            g_aw[((size_t)n*96 + l0 + l)*300 + d] = acc[l];
}

// ------------------- fusion GEMM + match input projection ------------------
__global__ void __launch_bounds__(320) k_fuse(const float* __restrict__ fusb,
                       const float* __restrict__ mbihf, const float* __restrict__ mbihb) {
    extern __shared__ float sm[];
    float* qa_s = sm;               // 16*304
    float* aw_s = sm + 16*304;
    float* qw_s = aw_s + 16*304;
    float* m_s  = qw_s + 16*304;
    int n = blockIdx.x, lt = blockIdx.y, l0 = lt*16;
    if (l0 >= g_len[n]) return;
    int tid = threadIdx.x;
    for (int i = tid; i < 16*300; i += blockDim.x) {
        int l = i/300, d = i%300;
        float q = g_qa[((size_t)n*96 + l0 + l)*300 + d];
        float a = g_aw[((size_t)n*96 + l0 + l)*300 + d];
        qa_s[l*304+d] = q; aw_s[l*304+d] = a; qw_s[l*304+d] = q*a;
    }
    __syncthreads();
    int lg = tid/75, jg = tid%75, j0 = jg*4;
    if (tid < 300) {
        ull acc2[4][4];
        #pragma unroll
        for (int li=0; li<4; li++)
            #pragma unroll
            for (int j=0; j<4; j++) acc2[li][j] = 0ull;
        #pragma unroll 2
        for (int d2 = 0; d2 < 150; d2++) {
            int wo = (d2*300 + j0)*2;
            ulonglong2 wa01 = *(const ulonglong2*)&g_WA2[wo];
            ulonglong2 wa23 = *(const ulonglong2*)&g_WA2[wo+4];
            ulonglong2 wb01 = *(const ulonglong2*)&g_WB2[wo];
            ulonglong2 wb23 = *(const ulonglong2*)&g_WB2[wo+4];
            ulonglong2 wc01 = *(const ulonglong2*)&g_WC2[wo];
            ulonglong2 wc23 = *(const ulonglong2*)&g_WC2[wo+4];
            #pragma unroll
            for (int li = 0; li < 4; li++) {
                int l = lg*4 + li;
                ull q2 = *(const ull*)&qa_s[l*304 + 2*d2];
                ull a2 = *(const ull*)&aw_s[l*304 + 2*d2];
                ull w2 = *(const ull*)&qw_s[l*304 + 2*d2];
                fma2(acc2[li][0], q2, wa01.x); fma2(acc2[li][1], q2, wa01.y);
                fma2(acc2[li][2], q2, wa23.x); fma2(acc2[li][3], q2, wa23.y);
                fma2(acc2[li][0], a2, wb01.x); fma2(acc2[li][1], a2, wb01.y);
                fma2(acc2[li][2], a2, wb23.x); fma2(acc2[li][3], a2, wb23.y);
                fma2(acc2[li][0], w2, wc01.x); fma2(acc2[li][1], w2, wc01.y);
                fma2(acc2[li][2], w2, wc23.x); fma2(acc2[li][3], w2, wc23.y);
            }
        }
        #pragma unroll
        for (int li=0; li<4; li++)
            #pragma unroll
            for (int j=0; j<4; j++) {
                float2 f = unpack2(acc2[li][j]);
                m_s[(lg*4+li)*304 + j0 + j] = tanhf(fusb[j0+j] + f.x + f.y);
            }
    }
    __syncthreads();
    if (tid < 300) {
        for (int c = 0; c < 4; c++) {
            int grp = c*75 + jg;
            if (grp >= 226) break;
            int jl0 = grp*4;
            int dir = jl0/452, g0 = jl0%452;
            const float* __restrict__ WM = g_mWihT2[dir];
            const float* __restrict__ mb = dir ? mbihb : mbihf;
            ull acc2[4][4];
            #pragma unroll
            for (int li=0; li<4; li++)
                #pragma unroll
                for (int j=0; j<4; j++) acc2[li][j] = 0ull;
            #pragma unroll 2
            for (int d2 = 0; d2 < 150; d2++) {
                int wo = (d2*452 + g0)*2;
                ulonglong2 w01 = *(const ulonglong2*)&WM[wo];
                ulonglong2 w23 = *(const ulonglong2*)&WM[wo+4];
                #pragma unroll
                for (int li = 0; li < 4; li++) {
                    ull mv2 = *(const ull*)&m_s[(lg*4+li)*304 + 2*d2];
                    fma2(acc2[li][0], mv2, w01.x); fma2(acc2[li][1], mv2, w01.y);
                    fma2(acc2[li][2], mv2, w23.x); fma2(acc2[li][3], mv2, w23.y);
                }
            }
            #pragma unroll
            for (int li=0; li<4; li++)
                #pragma unroll
                for (int j=0; j<4; j++)
                    if (g0+j < 450) {
                        float2 f = unpack2(acc2[li][j]);
                        g_xpm[dir][((size_t)(l0+lg*4+li)*320 + n)*450 + g0 + j]
                            = mb[g0+j] + f.x + f.y;
                    }
        }
    }
}

// ------------------------------ match GRU ----------------------------------
// NB_M=5 candidates per CTA -> 128 CTAs = one full wave.
__global__ void __launch_bounds__(480) k_mrnn(const float* __restrict__ bhhf,
                                              const float* __restrict__ bhhb) {
    extern __shared__ float sm[];
    float* Wsm = sm;                      // 450 * WPAD_M (thread-major)
    float* hs  = sm + 450*WPAD_M;         // NB_M*152
    float* hgs = hs + NB_M*152;           // NB_M*452
    float* xgs = hgs + NB_M*452;          // NB_M*452
    float* rms = xgs + NB_M*452;          // NB_M*152
    int dir = blockIdx.x / 64;
    int n0 = (blockIdx.x % 64) * NB_M;
    const float* __restrict__ WT = g_WhhT[2 + dir];
    const float* __restrict__ bhh = dir ? bhhb : bhhf;
    const float* __restrict__ xp = g_xpm[dir];
    int tid = threadIdx.x;
    for (int i = tid; i < 450*WSM_M; i += blockDim.x) {
        int e = i / 450, g2 = i % 450;
        Wsm[g2*WPAD_M + e] = WT[(WREG_M+e)*450 + g2];
    }
    for (int i = tid; i < NB_M*152; i += blockDim.x) hs[i] = 0.f;
    int lens[NB_M]; int maxlen = 0;
    #pragma unroll
    for (int ni = 0; ni < NB_M; ni++) { lens[ni] = g_len[n0+ni]; if (lens[ni] > maxlen) maxlen = lens[ni]; }
    for (int i = tid; i < NB_M*152; i += blockDim.x) {
        int ni = i/152;
        rms[i] = (lens[ni] < 96) ? 0.f : -1e30f;
    }
    int g = tid;
    ull wreg2[WREG_M/2];
    if (g < 450) {
        #pragma unroll
        for (int e2 = 0; e2 < WREG_M/2; e2++)
            wreg2[e2] = pack2(WT[(2*e2)*450 + g], WT[(2*e2+1)*450 + g]);
    }
    __syncthreads();
    float bias = (g < 450) ? bhh[g] : 0.f;
    const ulonglong2* wv = (const ulonglong2*)(Wsm + g*WPAD_M);
    float xnx[NB_M];
    if (g < 450) {
        #pragma unroll
        for (int ni = 0; ni < NB_M; ni++) {
            int li = dir ? (lens[ni]-1) : 0;
            if (li < 0) li = 0;
            if (li > 95) li = 95;
            xnx[ni] = xp[((size_t)li*320 + n0 + ni)*450 + g];
        }
    }
    for (int s = 0; s < maxlen; s++) {
        if (g < 450) {
            ull a2a[NB_M], a2b[NB_M];
            #pragma unroll
            for (int ni=0; ni<NB_M; ni++) { a2a[ni] = 0ull; a2b[ni] = 0ull; }
            #pragma unroll
            for (int e = 0; e < WREG_M; e += 4) {
                #pragma unroll
                for (int ni = 0; ni < NB_M; ni++) {
                    ulonglong2 hv = *(const ulonglong2*)&hs[ni*152 + e];
                    fma2(a2a[ni], hv.x, wreg2[e/2]);
                    fma2(a2b[ni], hv.y, wreg2[e/2+1]);
                }
            }
            #pragma unroll
            for (int e = 0; e < WSM_M; e += 4) {
                ulonglong2 wp = wv[e/4];
                #pragma unroll
                for (int ni = 0; ni < NB_M; ni++) {
                    ulonglong2 hv = *(const ulonglong2*)&hs[ni*152 + WREG_M + e];
                    fma2(a2a[ni], hv.x, wp.x);
                    fma2(a2b[ni], hv.y, wp.y);
                }
            }
            #pragma unroll
            for (int ni = 0; ni < NB_M; ni++) {
                float2 fa = unpack2(a2a[ni]), fb = unpack2(a2b[ni]);
                hgs[ni*452+g] = bias + (fa.x+fa.y) + (fb.x+fb.y);
                xgs[ni*452+g] = xnx[ni];
            }
        }
        __syncthreads();
        if (s + 1 < maxlen && g < 450) {
            #pragma unroll
            for (int ni = 0; ni < NB_M; ni++) {
                int li = dir ? (lens[ni]-2-s) : (s+1);
                if (li < 0) li = 0;
                if (li > 95) li = 95;
                xnx[ni] = xp[((size_t)li*320 + n0 + ni)*450 + g];
            }
        }
        if (g < 150) {
            #pragma unroll
            for (int ni = 0; ni < NB_M; ni++) {
                float m = (s < lens[ni]) ? 1.f : 0.f;
                float xr = xgs[ni*452+g], xz = xgs[ni*452+g+150], xn = xgs[ni*452+g+300];
                float hr = hgs[ni*452+g], hz = hgs[ni*452+g+150], hn = hgs[ni*452+g+300];
                float rr = 1.f/(1.f+expf(-(xr+hr)));
                float z  = 1.f/(1.f+expf(-(xz+hz)));
                float nn = tanhf(xn + rr*hn);
                float hp = hs[ni*152+g];
                float hnew = (1.f-z)*nn + z*hp;
                float o = m*hnew;
                hs[ni*152+g] = o + (1.f-m)*hp;
                rms[ni*152+g] = fmaxf(rms[ni*152+g], o);
            }
        }
        __syncthreads();
    }
    if (g < 150)
        for (int ni = 0; ni < NB_M; ni++)
            g_ans[(n0+ni)*300 + dir*150 + g] = rms[ni*152+g];
}

// ------------------------------ output -------------------------------------
__global__ void k_out(const float* __restrict__ outw, const float* __restrict__ outb,
                      float* __restrict__ out) {
    int b = blockIdx.x, w = threadIdx.x >> 5, lane = threadIdx.x & 31;
    __shared__ float lg[10];
    if (w < 10) {
        int n = b*10 + w;
        float s = 0.f;
        for (int d = lane; d < 300; d += 32) s += g_ans[n*300+d] * outw[d];
        for (int o = 16; o; o >>= 1) s += __shfl_xor_sync(0xffffffffu, s, o);
        if (lane == 0) lg[w] = s + outb[0];
    }
    __syncthreads();
    if (threadIdx.x == 0) {
        float mx = -1e30f;
        for (int k = 0; k < 10; k++) mx = fmaxf(mx, lg[k]);
        float ss = 0.f; float e[10];
        for (int k = 0; k < 10; k++) { e[k] = expf(lg[k]-mx); ss += e[k]; }
        for (int k = 0; k < 10; k++) out[b*10+k] = e[k]/ss;
    }
}

// ------------------------------ launch -------------------------------------
extern "C" void kernel_launch(void* const* d_in, const int* in_sizes, int n_in,
                              void* d_out, int out_size) {
    const int*   ctx   = (const int*)d_in[0];
    const int*   ques  = (const int*)d_in[1];
    const int*   ca    = (const int*)d_in[2];
    const float* emb   = (const float*)d_in[3];
    const float* eWihf = (const float*)d_in[4];
    const float* eWhhf = (const float*)d_in[5];
    const float* ebihf = (const float*)d_in[6];
    const float* ebhhf = (const float*)d_in[7];
    const float* eWihb = (const float*)d_in[8];
    const float* eWhhb = (const float*)d_in[9];
    const float* ebihb = (const float*)d_in[10];
    const float* ebhhb = (const float*)d_in[11];
    const float* mWihf = (const float*)d_in[12];
    const float* mWhhf = (const float*)d_in[13];
    const float* mbihf = (const float*)d_in[14];
    const float* mbhhf = (const float*)d_in[15];
    const float* mWihb = (const float*)d_in[16];
    const float* mWhhb = (const float*)d_in[17];
    const float* mbihb = (const float*)d_in[18];
    const float* mbhhb = (const float*)d_in[19];
    const float* fusW  = (const float*)d_in[20];
    const float* fusb  = (const float*)d_in[21];
    const float* outw  = (const float*)d_in[22];
    const float* outb  = (const float*)d_in[23];

    const int SM_ERNN = (480*WPAD_E + 2*152 + 400) * 4;
    const int SM_ATTN = (16*304 + 300*33 + 16*400) * 4;
    const int SM_FUSE = (4*16*304) * 4;
    const int SM_MRNN = (450*WPAD_M + NB_M*152 + NB_M*452 + NB_M*452 + NB_M*152) * 4;
    cudaFuncSetAttribute(k_ernn, cudaFuncAttributeMaxDynamicSharedMemorySize, SM_ERNN);
    cudaFuncSetAttribute(k_attn, cudaFuncAttributeMaxDynamicSharedMemorySize, SM_ATTN);
    cudaFuncSetAttribute(k_fuse, cudaFuncAttributeMaxDynamicSharedMemorySize, SM_FUSE);
    cudaFuncSetAttribute(k_mrnn, cudaFuncAttributeMaxDynamicSharedMemorySize, SM_MRNN);

    k_prep<<<256, 256>>>(ctx, ques, ca, eWihf, eWihb, eWhhf, eWhhb,
                         mWhhf, mWhhb, mWihf, mWihb, fusW);
    k_xp<<<464, 480>>>(ctx, ques, emb, ebihf, ebihb);
    k_ernn<<<128, 480, SM_ERNN>>>(ebhhf, ebhhb);
    k_attn<<<dim3(320,6), 320, SM_ATTN>>>(ca);
    k_fuse<<<dim3(320,6), 320, SM_FUSE>>>(fusb, mbihf, mbihb);
    k_mrnn<<<128, 480, SM_MRNN>>>(mbhhf, mbhhb);
    k_out<<<32, 320>>>(outw, outb, (float*)d_out);
}

// round 15
// speedup vs baseline: 1.1541x; 1.0907x over previous
#include <cuda_runtime.h>
#include <math.h>

#define WREG_E 72
#define WSM_E  80
#define WPAD_E 84
#define WREG_M 56
#define WSM_M  96
#define WPAD_M 100
#define NB_M   5

typedef unsigned long long ull;

__device__ __forceinline__ void fma2(ull& d, ull a, ull b) {
    asm("fma.rn.f32x2 %0, %1, %2, %0;" : "+l"(d) : "l"(a), "l"(b));
}
__device__ __forceinline__ float2 unpack2(ull v) {
    float2 r; asm("mov.b64 {%0,%1}, %2;" : "=f"(r.x), "=f"(r.y) : "l"(v)); return r;
}
__device__ __forceinline__ ull pack2(float lo, float hi) {
    ull p; asm("mov.b64 %0, {%1,%2};" : "=l"(p) : "f"(lo), "f"(hi)); return p;
}

// ------------------------------ scratch ------------------------------------
__device__ float g_xp[2][2][400*32*480];
__device__ float g_enc[2][400*32*300];
__device__ float g_ceT[32*300*400 + 64];     // [b][d][t] transposed ctx enc (+pad)
__device__ float g_qa[320*96*300];
__device__ float g_aw[320*96*300];
__device__ float g_xpm[2][96*320*450];
__device__ float g_ans[320*300];
__device__ float g_WihL2[2][150*480*2];
__device__ float g_mWihT2[2][150*452*2];
__device__ float g_WhhT[4][152*450];
__device__ float g_Wlane[2][152*480];
__device__ float g_WA2[150*300*2], g_WB2[150*300*2], g_WC2[150*300*2];
__device__ float g_cmask[32*400], g_qmask[32*64];
__device__ int   g_len[320];

// ------------------------------ prep ---------------------------------------
__global__ void k_prep(const int* ctx, const int* ques, const int* ca,
                       const float* eWihf, const float* eWihb,
                       const float* eWhhf, const float* eWhhb,
                       const float* mWhhf, const float* mWhhb,
                       const float* mWihf, const float* mWihb,
                       const float* fusW) {
    int t0 = blockIdx.x*blockDim.x + threadIdx.x;
    int stride = gridDim.x*blockDim.x;
    for (int i = t0; i < 2*150*480*2; i += stride) {
        int dir = i / (150*480*2);
        int rem = i % (150*480*2);
        int p = rem & 1, t = rem >> 1;
        int e2 = t / 480, idx = t % 480;
        int w = idx >> 5, l = idx & 31;
        float v = 0.f;
        if (l < 30) {
            int u = w*10 + l/3, q = l%3;
            int row = q*150 + u;
            v = (dir ? eWihb : eWihf)[row*300 + 2*e2 + p];
        }
        g_WihL2[dir][rem] = v;
    }
    for (int i = t0; i < 2*150*452*2; i += stride) {
        int dir = i / (150*452*2);
        int rem = i % (150*452*2);
        int p = rem & 1, t = rem >> 1;
        int d2 = t / 452, g = t % 452;
        float v = 0.f;
        if (g < 450) v = (dir ? mWihb : mWihf)[g*300 + 2*d2 + p];
        g_mWihT2[dir][rem] = v;
    }
    for (int i = t0; i < 152*450; i += stride) {
        int e = i/450, g = i%450;
        float c=0,d=0;
        if (e < 150) { c=mWhhf[g*150+e]; d=mWhhb[g*150+e]; }
        g_WhhT[2][i]=c; g_WhhT[3][i]=d;
    }
    for (int i = t0; i < 2*152*480; i += stride) {
        int dir = i / (152*480);
        int rem = i % (152*480);
        int e = rem / 480, idx = rem % 480;
        int w = idx >> 5, l = idx & 31;
        float v = 0.f;
        if (l < 30 && e < 150) {
            int u = w*10 + l/3, q = l%3;
            int row = q*150 + u;
            v = (dir ? eWhhb : eWhhf)[row*150 + e];
        }
        g_Wlane[dir][rem] = v;
    }
    for (int i = t0; i < 150*300*2; i += stride) {
        int p = i & 1, t = i >> 1;
        int d2 = t / 300, j = t % 300;
        int d = 2*d2 + p;
        const float* r = fusW + (size_t)j*1200;
        float w4 = r[900+d];
        g_WA2[i] = r[d] + w4;
        g_WB2[i] = r[300+d] - w4;
        g_WC2[i] = r[600+d];
    }
    for (int i = t0; i < 32*400; i += stride) g_cmask[i] = (ctx[i]!=0)?1.f:0.f;
    for (int i = t0; i < 32*64;  i += stride) g_qmask[i] = (ques[i]!=0)?1.f:0.f;
    for (int i = t0; i < 320; i += stride) {
        int bq = i/10;
        int c = 0;
        for (int t = 0; t < 64; t++) c += (ques[bq*64+t] != 0);
        int st = ca[i*2];
        int al = ca[i*2+1] - st;
        int len = al + c;
        if (len > 96) len = 96;
        g_len[i] = len;
    }
}

// ---------------------- encoder input projections --------------------------
__global__ void __launch_bounds__(480) k_xp(
        const int* __restrict__ ctx, const int* __restrict__ ques,
        const float* __restrict__ emb,
        const float* __restrict__ bihf, const float* __restrict__ bihb) {
    __shared__ float es[32][304];
    __shared__ int tok[32];
    int t = blockIdx.x;
    int seq = (t >= 400) ? 1 : 0;
    int ti = seq ? t-400 : t;
    int T = seq ? 64 : 400;
    const int* toks = seq ? ques : ctx;
    int tid = threadIdx.x;
    if (tid < 32) tok[tid] = toks[tid*T + ti];
    __syncthreads();
    for (int i = tid; i < 32*300; i += blockDim.x) {
        int b=i/300, e=i%300;
        es[b][e] = emb[(size_t)tok[b]*300 + e];
    }
    __syncthreads();
    int w = tid >> 5, l = tid & 31;
    bool active = (l < 30);
    int u = w*10 + l/3, q = l - (l/3)*3;
    int row = q*150 + u;
    for (int dir = 0; dir < 2; dir++) {
        const float* __restrict__ WT = g_WihL2[dir];
        float bias = active ? (dir ? bihb : bihf)[row] : 0.f;
        float* out = g_xp[seq][dir];
        for (int grp = 0; grp < 2; grp++) {
            int bb = grp*16;
            ull acc2[16];
            #pragma unroll
            for (int b=0;b<16;b++) acc2[b] = 0ull;
            for (int e2 = 0; e2 < 150; e2 += 2) {
                ull w2a = *(const ull*)&WT[(e2*480+tid)*2];
                ull w2b = *(const ull*)&WT[((e2+1)*480+tid)*2];
                #pragma unroll
                for (int b=0;b<16;b++) {
                    ulonglong2 v = *(const ulonglong2*)&es[bb+b][2*e2];
                    fma2(acc2[b], v.x, w2a);
                    fma2(acc2[b], v.y, w2b);
                }
            }
            #pragma unroll
            for (int b=0;b<16;b++) {
                float2 f = unpack2(acc2[b]);
                out[((size_t)ti*32+bb+b)*480 + tid] = bias + f.x + f.y;
            }
        }
    }
}

// ---------------------------- encoder GRU ----------------------------------
__global__ void __launch_bounds__(480) k_ernn(const float* __restrict__ bhhf,
                                              const float* __restrict__ bhhb) {
    extern __shared__ float sm[];
    float* Wsm = sm;
    float* hbuf = sm + 480*WPAD_E;
    float* msm = hbuf + 2*152;
    int id = blockIdx.x;
    int seq = (id >= 64) ? 1 : 0;
    int r = seq ? id-64 : id;
    int dir = r >> 5, b = r & 31;
    int T = seq ? 64 : 400;
    const float* __restrict__ WL = g_Wlane[dir];
    const float* __restrict__ bhh = dir ? bhhb : bhhf;
    const float* __restrict__ xp = g_xp[seq][dir];
    float* out = g_enc[seq];
    const float* __restrict__ mask = seq ? g_qmask : g_cmask;
    int tid = threadIdx.x;
    int w = tid >> 5, l = tid & 31;
    bool active = (l < 30);
    int u = w*10 + l/3;
    int q = l - (l/3)*3;
    int row = q*150 + u;

    for (int i = tid; i < 480*WSM_E; i += 480) {
        int j = i / WSM_E, e = i % WSM_E;
        Wsm[j*WPAD_E + e] = WL[(WREG_E+e)*480 + j];
    }
    for (int i = tid; i < 2*152; i += 480) hbuf[i] = 0.f;
    for (int i = tid; i < T; i += 480) msm[i] = mask[b*T + i];
    ull wreg2[WREG_E/2];
    #pragma unroll
    for (int e2 = 0; e2 < WREG_E/2; e2++)
        wreg2[e2] = pack2(WL[(2*e2)*480 + tid], WL[(2*e2+1)*480 + tid]);
    float bias = active ? bhh[row] : 0.f;
    __syncthreads();

    const ulonglong2* wv = (const ulonglong2*)(Wsm + tid*WPAD_E);
    int cur = 0;
    int tt0 = dir ? (T-1) : 0;
    float xnext = xp[((size_t)tt0*32+b)*480 + tid];
    for (int s = 0; s < T; s++) {
        int tt = dir ? (T-1-s) : s;
        float xg = xnext;
        const float* hcur = hbuf + cur*152;
        ull a0 = 0ull, a1 = 0ull, a2 = 0ull, a3 = 0ull;
        #pragma unroll
        for (int e = 0; e < WREG_E; e += 8) {
            ulonglong2 h1 = *(const ulonglong2*)&hcur[e];
            ulonglong2 h2 = *(const ulonglong2*)&hcur[e+4];
            fma2(a0, h1.x, wreg2[e/2]);
            fma2(a1, h1.y, wreg2[e/2+1]);
            fma2(a2, h2.x, wreg2[e/2+2]);
            fma2(a3, h2.y, wreg2[e/2+3]);
        }
        #pragma unroll
        for (int e = 0; e < WSM_E; e += 8) {
            ulonglong2 w1 = wv[e/4];
            ulonglong2 w2 = wv[e/4+1];
            ulonglong2 h1 = *(const ulonglong2*)&hcur[WREG_E+e];
            ulonglong2 h2 = *(const ulonglong2*)&hcur[WREG_E+e+4];
            fma2(a0, h1.x, w1.x);
            fma2(a1, h1.y, w1.y);
            fma2(a2, h2.x, w2.x);
            fma2(a3, h2.y, w2.y);
        }
        float2 f0 = unpack2(a0), f1 = unpack2(a1), f2 = unpack2(a2), f3 = unpack2(a3);
        float hd = bias + ((f0.x+f0.y)+(f1.x+f1.y)) + ((f2.x+f2.y)+(f3.x+f3.y));
        if (s + 1 < T) {
            int tn = dir ? (T-2-s) : (s+1);
            xnext = xp[((size_t)tn*32+b)*480 + tid];
        }
        int base = (l/3)*3;
        float hd_r = __shfl_sync(0xffffffffu, hd, base);
        float hd_z = __shfl_sync(0xffffffffu, hd, base+1);
        float hd_n = __shfl_sync(0xffffffffu, hd, base+2);
        float xg_r = __shfl_sync(0xffffffffu, xg, base);
        float xg_z = __shfl_sync(0xffffffffu, xg, base+1);
        float xg_n = __shfl_sync(0xffffffffu, xg, base+2);
        if (active) {
            float m  = msm[tt];
            float rr = 1.f/(1.f+expf(-(xg_r+hd_r)));
            float z  = 1.f/(1.f+expf(-(xg_z+hd_z)));
            float nn = tanhf(xg_n + rr*hd_n);
            float hp = hcur[u];
            float hnew = (1.f-z)*nn + z*hp;
            float o = m*hnew;
            if (q == 0) {
                hbuf[(cur^1)*152 + u] = o + (1.f-m)*hp;
                out[((size_t)tt*32+b)*300 + dir*150 + u] = o;
            }
        }
        cur ^= 1;
        __syncthreads();
    }
}

// -------------------- transpose ctx enc: (t,b,d) -> (b,d,t) -----------------
__global__ void k_tr() {
    __shared__ float ts[32][33];
    int b = blockIdx.z;
    int t0 = blockIdx.x*32, d0 = blockIdx.y*32;
    int tx = threadIdx.x, ty = threadIdx.y;
    int t = t0+ty, d = d0+tx;
    if (t < 400 && d < 300) ts[ty][tx] = g_enc[0][((size_t)t*32+b)*300 + d];
    __syncthreads();
    int dd = d0+ty, tt = t0+tx;
    if (dd < 300 && tt < 400) g_ceT[((size_t)b*300+dd)*400 + tt] = ts[tx][ty];
}

// -------------------- attention (no in-kernel transposes) -------------------
__global__ void __launch_bounds__(320) k_attn(const int* __restrict__ ca) {
    extern __shared__ float sm[];
    float* qa_s = sm;              // 16*304
    float* sc   = sm + 16*304;     // 16*400
    int n = blockIdx.x, lt = blockIdx.y, l0 = lt*16;
    int len = g_len[n];
    if (l0 >= len) return;
    int b = n/10;
    int st = ca[n*2], alen = ca[n*2+1] - st;
    int tid = threadIdx.x, warp = tid>>5, lane = tid&31;
    // gather qa tile (and persist to g_qa for k_fuse)
    for (int i = tid; i < 16*300; i += 320) {
        int l = i/300, d = i%300;
        int gl = l0 + l;
        float v = 0.f;
        if (gl < len) {
            if (gl < alen) {
                int t = st + gl; if (t > 399) t = 399;
                v = g_enc[0][((size_t)t*32+b)*300 + d];
            } else {
                int t = gl - alen; if (t > 63) t = 63;
                v = g_enc[1][((size_t)t*32+b)*300 + d];
            }
        }
        qa_s[l*304+d] = v;
        g_qa[((size_t)n*96+gl)*300 + d] = v;
    }
    __syncthreads();
    // pass 1: scores — direct coalesced global reads from g_ceT
    if (warp < 8) {
        int L0 = warp, L1 = warp + 8;
        const float* __restrict__ ct = &g_ceT[(size_t)b*300*400];
        const float* qa0 = &qa_s[L0*304];
        const float* qa1 = &qa_s[L1*304];
        for (int t0 = 0; t0 < 400; t0 += 32) {
            int t = t0 + lane;
            float a0 = 0.f, a1 = 0.f;
            #pragma unroll 10
            for (int d = 0; d < 300; d++) {
                float c = ct[(size_t)d*400 + t];
                a0 += qa0[d]*c;
                a1 += qa1[d]*c;
            }
            if (t < 400) {
                float cm = g_cmask[b*400 + t];
                float big = -1e30f;
                sc[L0*400+t] = cm>0.f ? a0 : big;
                sc[L1*400+t] = cm>0.f ? a1 : big;
            }
        }
    }
    __syncthreads();
    // softmax per row
    for (int l = warp; l < 16; l += 10) {
        float mx = -1e30f;
        for (int t = lane; t < 400; t += 32) mx = fmaxf(mx, sc[l*400+t]);
        for (int o = 16; o; o >>= 1) mx = fmaxf(mx, __shfl_xor_sync(0xffffffffu, mx, o));
        float ss = 0.f;
        for (int t = lane; t < 400; t += 32) { float e = expf(sc[l*400+t]-mx); sc[l*400+t]=e; ss += e; }
        for (int o = 16; o; o >>= 1) ss += __shfl_xor_sync(0xffffffffu, ss, o);
        float inv = 1.f/ss;
        for (int t = lane; t < 400; t += 32) sc[l*400+t] *= inv;
    }
    __syncthreads();
    // pass 2: aware — direct coalesced global reads from g_enc
    int d = tid;
    if (d < 300) {
        float acc[16];
        #pragma unroll
        for (int l = 0; l < 16; l++) acc[l] = 0.f;
        const float* __restrict__ ce = &g_enc[0][(size_t)b*300 + d];
        for (int t = 0; t < 400; t += 4) {
            float c0 = ce[(size_t)(t  )*9600];
            float c1 = ce[(size_t)(t+1)*9600];
            float c2 = ce[(size_t)(t+2)*9600];
            float c3 = ce[(size_t)(t+3)*9600];
            #pragma unroll
            for (int l = 0; l < 16; l++) {
                float4 al = *(const float4*)&sc[l*400 + t];
                acc[l] += al.x*c0 + al.y*c1 + al.z*c2 + al.w*c3;
            }
        }
        for (int l = 0; l < 16; l++)
            g_aw[((size_t)n*96 + l0 + l)*300 + d] = acc[l];
    }
}

// ------------------- fusion GEMM + match input projection ------------------
__global__ void __launch_bounds__(320) k_fuse(const float* __restrict__ fusb,
                       const float* __restrict__ mbihf, const float* __restrict__ mbihb) {
    extern __shared__ float sm[];
    float* qa_s = sm;               // 16*304
    float* aw_s = sm + 16*304;
    float* qw_s = aw_s + 16*304;
    float* m_s  = qw_s + 16*304;
    int n = blockIdx.x, lt = blockIdx.y, l0 = lt*16;
    if (l0 >= g_len[n]) return;
    int tid = threadIdx.x;
    for (int i = tid; i < 16*300; i += blockDim.x) {
        int l = i/300, d = i%300;
        float q = g_qa[((size_t)n*96 + l0 + l)*300 + d];
        float a = g_aw[((size_t)n*96 + l0 + l)*300 + d];
        qa_s[l*304+d] = q; aw_s[l*304+d] = a; qw_s[l*304+d] = q*a;
    }
    __syncthreads();
    int lg = tid/75, jg = tid%75, j0 = jg*4;
    if (tid < 300) {
        ull acc2[4][4];
        #pragma unroll
        for (int li=0; li<4; li++)
            #pragma unroll
            for (int j=0; j<4; j++) acc2[li][j] = 0ull;
        #pragma unroll 2
        for (int d2 = 0; d2 < 150; d2++) {
            int wo = (d2*300 + j0)*2;
            ulonglong2 wa01 = *(const ulonglong2*)&g_WA2[wo];
            ulonglong2 wa23 = *(const ulonglong2*)&g_WA2[wo+4];
            ulonglong2 wb01 = *(const ulonglong2*)&g_WB2[wo];
            ulonglong2 wb23 = *(const ulonglong2*)&g_WB2[wo+4];
            ulonglong2 wc01 = *(const ulonglong2*)&g_WC2[wo];
            ulonglong2 wc23 = *(const ulonglong2*)&g_WC2[wo+4];
            #pragma unroll
            for (int li = 0; li < 4; li++) {
                int l = lg*4 + li;
                ull q2 = *(const ull*)&qa_s[l*304 + 2*d2];
                ull a2 = *(const ull*)&aw_s[l*304 + 2*d2];
                ull w2 = *(const ull*)&qw_s[l*304 + 2*d2];
                fma2(acc2[li][0], q2, wa01.x); fma2(acc2[li][1], q2, wa01.y);
                fma2(acc2[li][2], q2, wa23.x); fma2(acc2[li][3], q2, wa23.y);
                fma2(acc2[li][0], a2, wb01.x); fma2(acc2[li][1], a2, wb01.y);
                fma2(acc2[li][2], a2, wb23.x); fma2(acc2[li][3], a2, wb23.y);
                fma2(acc2[li][0], w2, wc01.x); fma2(acc2[li][1], w2, wc01.y);
                fma2(acc2[li][2], w2, wc23.x); fma2(acc2[li][3], w2, wc23.y);
            }
        }
        #pragma unroll
        for (int li=0; li<4; li++)
            #pragma unroll
            for (int j=0; j<4; j++) {
                float2 f = unpack2(acc2[li][j]);
                m_s[(lg*4+li)*304 + j0 + j] = tanhf(fusb[j0+j] + f.x + f.y);
            }
    }
    __syncthreads();
    if (tid < 300) {
        for (int c = 0; c < 4; c++) {
            int grp = c*75 + jg;
            if (grp >= 226) break;
            int jl0 = grp*4;
            int dir = jl0/452, g0 = jl0%452;
            const float* __restrict__ WM = g_mWihT2[dir];
            const float* __restrict__ mb = dir ? mbihb : mbihf;
            ull acc2[4][4];
            #pragma unroll
            for (int li=0; li<4; li++)
                #pragma unroll
                for (int j=0; j<4; j++) acc2[li][j] = 0ull;
            #pragma unroll 2
            for (int d2 = 0; d2 < 150; d2++) {
                int wo = (d2*452 + g0)*2;
                ulonglong2 w01 = *(const ulonglong2*)&WM[wo];
                ulonglong2 w23 = *(const ulonglong2*)&WM[wo+4];
                #pragma unroll
                for (int li = 0; li < 4; li++) {
                    ull mv2 = *(const ull*)&m_s[(lg*4+li)*304 + 2*d2];
                    fma2(acc2[li][0], mv2, w01.x); fma2(acc2[li][1], mv2, w01.y);
                    fma2(acc2[li][2], mv2, w23.x); fma2(acc2[li][3], mv2, w23.y);
                }
            }
            #pragma unroll
            for (int li=0; li<4; li++)
                #pragma unroll
                for (int j=0; j<4; j++)
                    if (g0+j < 450) {
                        float2 f = unpack2(acc2[li][j]);
                        g_xpm[dir][((size_t)(l0+lg*4+li)*320 + n)*450 + g0 + j]
                            = mb[g0+j] + f.x + f.y;
                    }
        }
    }
}

// ------------------------------ match GRU ----------------------------------
__global__ void __launch_bounds__(480) k_mrnn(const float* __restrict__ bhhf,
                                              const float* __restrict__ bhhb) {
    extern __shared__ float sm[];
    float* Wsm = sm;
    float* hs  = sm + 450*WPAD_M;
    float* hgs = hs + NB_M*152;
    float* xgs = hgs + NB_M*452;
    float* rms = xgs + NB_M*452;
    int dir = blockIdx.x / 64;
    int n0 = (blockIdx.x % 64) * NB_M;
    const float* __restrict__ WT = g_WhhT[2 + dir];
    const float* __restrict__ bhh = dir ? bhhb : bhhf;
    const float* __restrict__ xp = g_xpm[dir];
    int tid = threadIdx.x;
    for (int i = tid; i < 450*WSM_M; i += blockDim.x) {
        int e = i / 450, g2 = i % 450;
        Wsm[g2*WPAD_M + e] = WT[(WREG_M+e)*450 + g2];
    }
    for (int i = tid; i < NB_M*152; i += blockDim.x) hs[i] = 0.f;
    int lens[NB_M]; int maxlen = 0;
    #pragma unroll
    for (int ni = 0; ni < NB_M; ni++) { lens[ni] = g_len[n0+ni]; if (lens[ni] > maxlen) maxlen = lens[ni]; }
    for (int i = tid; i < NB_M*152; i += blockDim.x) {
        int ni = i/152;
        rms[i] = (lens[ni] < 96) ? 0.f : -1e30f;
    }
    int g = tid;
    ull wreg2[WREG_M/2];
    if (g < 450) {
        #pragma unroll
        for (int e2 = 0; e2 < WREG_M/2; e2++)
            wreg2[e2] = pack2(WT[(2*e2)*450 + g], WT[(2*e2+1)*450 + g]);
    }
    __syncthreads();
    float bias = (g < 450) ? bhh[g] : 0.f;
    const ulonglong2* wv = (const ulonglong2*)(Wsm + g*WPAD_M);
    float xnx[NB_M];
    if (g < 450) {
        #pragma unroll
        for (int ni = 0; ni < NB_M; ni++) {
            int li = dir ? (lens[ni]-1) : 0;
            if (li < 0) li = 0;
            if (li > 95) li = 95;
            xnx[ni] = xp[((size_t)li*320 + n0 + ni)*450 + g];
        }
    }
    for (int s = 0; s < maxlen; s++) {
        if (g < 450) {
            ull a2a[NB_M], a2b[NB_M];
            #pragma unroll
            for (int ni=0; ni<NB_M; ni++) { a2a[ni] = 0ull; a2b[ni] = 0ull; }
            #pragma unroll
            for (int e = 0; e < WREG_M; e += 4) {
                #pragma unroll
                for (int ni = 0; ni < NB_M; ni++) {
                    ulonglong2 hv = *(const ulonglong2*)&hs[ni*152 + e];
                    fma2(a2a[ni], hv.x, wreg2[e/2]);
                    fma2(a2b[ni], hv.y, wreg2[e/2+1]);
                }
            }
            #pragma unroll
            for (int e = 0; e < WSM_M; e += 4) {
                ulonglong2 wp = wv[e/4];
                #pragma unroll
                for (int ni = 0; ni < NB_M; ni++) {
                    ulonglong2 hv = *(const ulonglong2*)&hs[ni*152 + WREG_M + e];
                    fma2(a2a[ni], hv.x, wp.x);
                    fma2(a2b[ni], hv.y, wp.y);
                }
            }
            #pragma unroll
            for (int ni = 0; ni < NB_M; ni++) {
                float2 fa = unpack2(a2a[ni]), fb = unpack2(a2b[ni]);
                hgs[ni*452+g] = bias + (fa.x+fa.y) + (fb.x+fb.y);
                xgs[ni*452+g] = xnx[ni];
            }
        }
        __syncthreads();
        if (s + 1 < maxlen && g < 450) {
            #pragma unroll
            for (int ni = 0; ni < NB_M; ni++) {
                int li = dir ? (lens[ni]-2-s) : (s+1);
                if (li < 0) li = 0;
                if (li > 95) li = 95;
                xnx[ni] = xp[((size_t)li*320 + n0 + ni)*450 + g];
            }
        }
        if (g < 150) {
            #pragma unroll
            for (int ni = 0; ni < NB_M; ni++) {
                float m = (s < lens[ni]) ? 1.f : 0.f;
                float xr = xgs[ni*452+g], xz = xgs[ni*452+g+150], xn = xgs[ni*452+g+300];
                float hr = hgs[ni*452+g], hz = hgs[ni*452+g+150], hn = hgs[ni*452+g+300];
                float rr = 1.f/(1.f+expf(-(xr+hr)));
                float z  = 1.f/(1.f+expf(-(xz+hz)));
                float nn = tanhf(xn + rr*hn);
                float hp = hs[ni*152+g];
                float hnew = (1.f-z)*nn + z*hp;
                float o = m*hnew;
                hs[ni*152+g] = o + (1.f-m)*hp;
                rms[ni*152+g] = fmaxf(rms[ni*152+g], o);
            }
        }
        __syncthreads();
    }
    if (g < 150)
        for (int ni = 0; ni < NB_M; ni++)
            g_ans[(n0+ni)*300 + dir*150 + g] = rms[ni*152+g];
}

// ------------------------------ output -------------------------------------
__global__ void k_out(const float* __restrict__ outw, const float* __restrict__ outb,
                      float* __restrict__ out) {
    int b = blockIdx.x, w = threadIdx.x >> 5, lane = threadIdx.x & 31;
    __shared__ float lg[10];
    if (w < 10) {
        int n = b*10 + w;
        float s = 0.f;
        for (int d = lane; d < 300; d += 32) s += g_ans[n*300+d] * outw[d];
        for (int o = 16; o; o >>= 1) s += __shfl_xor_sync(0xffffffffu, s, o);
        if (lane == 0) lg[w] = s + outb[0];
    }
    __syncthreads();
    if (threadIdx.x == 0) {
        float mx = -1e30f;
        for (int k = 0; k < 10; k++) mx = fmaxf(mx, lg[k]);
        float ss = 0.f; float e[10];
        for (int k = 0; k < 10; k++) { e[k] = expf(lg[k]-mx); ss += e[k]; }
        for (int k = 0; k < 10; k++) out[b*10+k] = e[k]/ss;
    }
}

// ------------------------------ launch -------------------------------------
extern "C" void kernel_launch(void* const* d_in, const int* in_sizes, int n_in,
                              void* d_out, int out_size) {
    const int*   ctx   = (const int*)d_in[0];
    const int*   ques  = (const int*)d_in[1];
    const int*   ca    = (const int*)d_in[2];
    const float* emb   = (const float*)d_in[3];
    const float* eWihf = (const float*)d_in[4];
    const float* eWhhf = (const float*)d_in[5];
    const float* ebihf = (const float*)d_in[6];
    const float* ebhhf = (const float*)d_in[7];
    const float* eWihb = (const float*)d_in[8];
    const float* eWhhb = (const float*)d_in[9];
    const float* ebihb = (const float*)d_in[10];
    const float* ebhhb = (const float*)d_in[11];
    const float* mWihf = (const float*)d_in[12];
    const float* mWhhf = (const float*)d_in[13];
    const float* mbihf = (const float*)d_in[14];
    const float* mbhhf = (const float*)d_in[15];
    const float* mWihb = (const float*)d_in[16];
    const float* mWhhb = (const float*)d_in[17];
    const float* mbihb = (const float*)d_in[18];
    const float* mbhhb = (const float*)d_in[19];
    const float* fusW  = (const float*)d_in[20];
    const float* fusb  = (const float*)d_in[21];
    const float* outw  = (const float*)d_in[22];
    const float* outb  = (const float*)d_in[23];

    const int SM_ERNN = (480*WPAD_E + 2*152 + 400) * 4;
    const int SM_ATTN = (16*304 + 16*400) * 4;
    const int SM_FUSE = (4*16*304) * 4;
    const int SM_MRNN = (450*WPAD_M + NB_M*152 + NB_M*452 + NB_M*452 + NB_M*152) * 4;
    cudaFuncSetAttribute(k_ernn, cudaFuncAttributeMaxDynamicSharedMemorySize, SM_ERNN);
    cudaFuncSetAttribute(k_attn, cudaFuncAttributeMaxDynamicSharedMemorySize, SM_ATTN);
    cudaFuncSetAttribute(k_fuse, cudaFuncAttributeMaxDynamicSharedMemorySize, SM_FUSE);
    cudaFuncSetAttribute(k_mrnn, cudaFuncAttributeMaxDynamicSharedMemorySize, SM_MRNN);

    k_prep<<<256, 256>>>(ctx, ques, ca, eWihf, eWihb, eWhhf, eWhhb,
                         mWhhf, mWhhb, mWihf, mWihb, fusW);
    k_xp<<<464, 480>>>(ctx, ques, emb, ebihf, ebihb);
    k_ernn<<<128, 480, SM_ERNN>>>(ebhhf, ebhhb);
    k_tr<<<dim3(13,10,32), dim3(32,32)>>>();
    k_attn<<<dim3(320,6), 320, SM_ATTN>>>(ca);
    k_fuse<<<dim3(320,6), 320, SM_FUSE>>>(fusb, mbihf, mbihb);
    k_mrnn<<<128, 480, SM_MRNN>>>(mbhhf, mbhhb);
    k_out<<<32, 320>>>(outw, outb, (float*)d_out);
}